// round 11
// baseline (speedup 1.0000x reference)
#include <cuda_runtime.h>
#include <cuda_bf16.h>
#include <math.h>
#include <float.h>

#define NPTS 2048
#define KNN  10
#define OUTF 256
#define NTILES 64                 // 2048 / 32
#define NTPAIRS 2080              // 64*65/2
#define NCOLS (NTILES * 2)        // part slots per row (2 step-halves per tile)

// _rn intrinsics: immune to compiler fast-math; used on all eigen/kNN-critical math
#define FMUL(a,b)  __fmul_rn((a),(b))
#define FADD(a,b)  __fadd_rn((a),(b))
#define FSUB(a,b)  __fsub_rn((a),(b))
#define FDIV(a,b)  __fdiv_rn((a),(b))
#define FSQRT(a)   __fsqrt_rn((a))

// SoA: [0..N)=px [N..2N)=py [2N..3N)=pz [3N..4N)=nx [4N..5N)=ny [5N..6N)=nz [6N..7N)=|n|^2
__device__ float  g_soa[NPTS * 7];
// covariance scratch, SoA: 6 slices of NPTS
__device__ float  g_cov[NPTS * 6];
// per-(row, col-slot) partial PPF sums; single writer per slot (deterministic)
__device__ float4 g_part[NPTS * NCOLS];

// ---------------------------------------------------------------------------
// LAPACK fp32 building blocks (netlib-faithful, LAPACK >= 3.10 conventions)
// ---------------------------------------------------------------------------

__device__ __forceinline__ float f_sign(float a, float b) {
    return (b >= 0.f) ? fabsf(a) : -fabsf(a);
}

__device__ __forceinline__ float slapy2f(float x, float y) {
    float xa = fabsf(x), ya = fabsf(y);
    float w = fmaxf(xa, ya), z = fminf(xa, ya);
    if (z == 0.f) return w;
    float t = FDIV(z, w);
    return FMUL(w, FSQRT(FADD(1.f, FMUL(t, t))));
}

__device__ __forceinline__ void slartgf(float f, float g, float* c, float* s, float* r) {
    if (g == 0.f)      { *c = 1.f; *s = 0.f; *r = f; }
    else if (f == 0.f) { *c = 0.f; *s = (g >= 0.f) ? 1.f : -1.f; *r = fabsf(g); }
    else {
        float d  = FSQRT(FADD(FMUL(f, f), FMUL(g, g)));
        float rr = (f >= 0.f) ? d : -d;
        *c = FDIV(fabsf(f), d);
        *s = FDIV(g, rr);
        *r = rr;
    }
}

__device__ void slaev2f(float a, float b, float c,
                        float* rt1, float* rt2, float* cs1, float* sn1) {
    float sm  = FADD(a, c);
    float df  = FSUB(a, c);
    float adf = fabsf(df);
    float tb  = FADD(b, b);
    float ab  = fabsf(tb);
    float acmx, acmn;
    if (fabsf(a) > fabsf(c)) { acmx = a; acmn = c; } else { acmx = c; acmn = a; }
    float rt;
    if (adf > ab) {
        float t = FDIV(ab, adf);
        rt = FMUL(adf, FSQRT(FADD(1.f, FMUL(t, t))));
    } else if (adf < ab) {
        float t = FDIV(adf, ab);
        rt = FMUL(ab, FSQRT(FADD(1.f, FMUL(t, t))));
    } else {
        rt = FMUL(ab, FSQRT(2.f));
    }
    int sgn1;
    if (sm < 0.f) {
        *rt1 = FMUL(0.5f, FSUB(sm, rt)); sgn1 = -1;
        *rt2 = FSUB(FMUL(FDIV(acmx, *rt1), acmn), FMUL(FDIV(b, *rt1), b));
    } else if (sm > 0.f) {
        *rt1 = FMUL(0.5f, FADD(sm, rt)); sgn1 = 1;
        *rt2 = FSUB(FMUL(FDIV(acmx, *rt1), acmn), FMUL(FDIV(b, *rt1), b));
    } else {
        *rt1 = FMUL(0.5f, rt); *rt2 = FMUL(-0.5f, rt); sgn1 = 1;
    }
    float cs; int sgn2;
    if (df >= 0.f) { cs = FADD(df, rt); sgn2 =  1; }
    else           { cs = FSUB(df, rt); sgn2 = -1; }
    float acs = fabsf(cs);
    if (acs > ab) {
        float ct = FDIV(-tb, cs);
        *sn1 = FDIV(1.f, FSQRT(FADD(1.f, FMUL(ct, ct))));
        *cs1 = FMUL(ct, *sn1);
    } else {
        if (ab == 0.f) { *cs1 = 1.f; *sn1 = 0.f; }
        else {
            float tn = FDIV(-cs, tb);
            *cs1 = FDIV(1.f, FSQRT(FADD(1.f, FMUL(tn, tn))));
            *sn1 = FMUL(tn, *cs1);
        }
    }
    if (sgn1 == sgn2) { float tn = *cs1; *cs1 = -(*sn1); *sn1 = tn; }
}

// ssteqr('I', n=3), register-resident; control flow/arithmetic == netlib
__device__ void ssteqr3_reg(float& d0, float& d1, float& d2,
                            float& e0, float& e1,
                            float& za0, float& za1, float& za2,
                            float& zb0, float& zb1, float& zb2,
                            float& zc0, float& zc1, float& zc2) {
    const float eps    = 5.9604645e-8f;
    const float eps2   = eps * eps;
    const float safmin = 1.17549435e-38f;
    float wc0 = 0.f, wc1 = 0.f, ws0 = 0.f, ws1 = 0.f;

    auto dget = [&](int i) -> float { return i == 0 ? d0 : (i == 1 ? d1 : d2); };
    auto dset = [&](int i, float v) { if (i == 0) d0 = v; else if (i == 1) d1 = v; else d2 = v; };
    auto eget = [&](int i) -> float { return i == 0 ? e0 : e1; };
    auto eset = [&](int i, float v) { if (i == 0) e0 = v; else e1 = v; };
    auto wcget = [&](int i) -> float { return i == 0 ? wc0 : wc1; };
    auto wcset = [&](int i, float v) { if (i == 0) wc0 = v; else wc1 = v; };
    auto wsget = [&](int i) -> float { return i == 0 ? ws0 : ws1; };
    auto wsset = [&](int i, float v) { if (i == 0) ws0 = v; else ws1 = v; };

    auto rot = [&](int cb1, float c, float s) {
        if (cb1 == 1) {
            float t;
            t = zb0; zb0 = FSUB(FMUL(c, t), FMUL(s, za0)); za0 = FADD(FMUL(s, t), FMUL(c, za0));
            t = zb1; zb1 = FSUB(FMUL(c, t), FMUL(s, za1)); za1 = FADD(FMUL(s, t), FMUL(c, za1));
            t = zb2; zb2 = FSUB(FMUL(c, t), FMUL(s, za2)); za2 = FADD(FMUL(s, t), FMUL(c, za2));
        } else {
            float t;
            t = zc0; zc0 = FSUB(FMUL(c, t), FMUL(s, zb0)); zb0 = FADD(FMUL(s, t), FMUL(c, zb0));
            t = zc1; zc1 = FSUB(FMUL(c, t), FMUL(s, zb1)); zb1 = FADD(FMUL(s, t), FMUL(c, zb1));
            t = zc2; zc2 = FSUB(FMUL(c, t), FMUL(s, zb2)); zb2 = FADD(FMUL(s, t), FMUL(c, zb2));
        }
    };
    auto slasr_bL = [&](int lcol, int mm) {
        for (int j = mm - 1; j >= 1; --j) {
            float c = wcget(lcol - 2 + j), s = wsget(lcol - 2 + j);
            if (c != 1.f || s != 0.f) rot(lcol + j - 1, c, s);
        }
    };
    auto slasr_fL = [&](int lcol, int mm) {
        for (int j = 1; j <= mm - 1; ++j) {
            float c = wcget(lcol - 2 + j), s = wsget(lcol - 2 + j);
            if (c != 1.f || s != 0.f) rot(lcol + j - 1, c, s);
        }
    };

    int l1, l, lsv, lend, lendsv, m, i, jtot, nmaxit;
    float p, g, r, s, c, f, bb, rt1, rt2, anorm, tst;
    nmaxit = 90; jtot = 0; l1 = 1;

L10:
    if (l1 > 3) goto L160;
    if (l1 > 1) eset(l1 - 2, 0.f);
    if (l1 <= 2) {
        for (m = l1; m <= 2; ++m) {
            tst = fabsf(eget(m - 1));
            if (tst == 0.f) goto L30;
            if (tst <= FMUL(FMUL(FSQRT(fabsf(dget(m - 1))), FSQRT(fabsf(dget(m)))), eps)) {
                eset(m - 1, 0.f); goto L30;
            }
        }
    }
    m = 3;
L30:
    l = l1; lsv = l; lend = m; lendsv = lend; l1 = m + 1;
    if (lend == l) goto L10;
    anorm = 0.f;
    for (i = l; i <= lend; ++i)     anorm = fmaxf(anorm, fabsf(dget(i - 1)));
    for (i = l; i <= lend - 1; ++i) anorm = fmaxf(anorm, fabsf(eget(i - 1)));
    if (anorm == 0.f) goto L10;
    if (fabsf(dget(lend - 1)) < fabsf(dget(l - 1))) { lend = lsv; l = lendsv; }
    if (lend > l) goto L40; else goto L90;

L40: // QL
    if (l != lend) {
        for (m = l; m <= lend - 1; ++m) {
            tst = FMUL(eget(m - 1), eget(m - 1));
            if (tst <= FADD(FMUL(FMUL(eps2, fabsf(dget(m - 1))), fabsf(dget(m))), safmin)) goto L60;
        }
    }
    m = lend;
L60:
    if (m < lend) eset(m - 1, 0.f);
    p = dget(l - 1);
    if (m == l) goto L80;
    if (m == l + 1) {
        slaev2f(dget(l - 1), eget(l - 1), dget(l), &rt1, &rt2, &c, &s);
        wcset(l - 1, c); wsset(l - 1, s);
        slasr_bL(l, 2);
        dset(l - 1, rt1); dset(l, rt2); eset(l - 1, 0.f);
        l += 2;
        if (l <= lend) goto L40;
        goto L140;
    }
    if (jtot == nmaxit) goto L140;
    jtot++;
    g = FDIV(FSUB(dget(l), p), FMUL(2.f, eget(l - 1)));
    r = slapy2f(g, 1.f);
    g = FADD(FSUB(dget(m - 1), p), FDIV(eget(l - 1), FADD(g, f_sign(r, g))));
    s = 1.f; c = 1.f; p = 0.f;
    for (i = m - 1; i >= l; --i) {
        f  = FMUL(s, eget(i - 1));
        bb = FMUL(c, eget(i - 1));
        slartgf(g, f, &c, &s, &r);
        if (i != m - 1) eset(i, r);
        g = FSUB(dget(i), p);
        r = FADD(FMUL(FSUB(dget(i - 1), g), s), FMUL(FMUL(2.f, c), bb));
        p = FMUL(s, r);
        dset(i, FADD(g, p));
        g = FSUB(FMUL(c, r), bb);
        wcset(i - 1, c); wsset(i - 1, -s);
    }
    slasr_bL(l, m - l + 1);
    dset(l - 1, FSUB(dget(l - 1), p));
    eset(l - 1, g);
    goto L40;
L80:
    dset(l - 1, p);
    l++;
    if (l <= lend) goto L40;
    goto L140;

L90: // QR
    if (l != lend) {
        for (m = l; m >= lend + 1; --m) {
            tst = FMUL(eget(m - 2), eget(m - 2));
            if (tst <= FADD(FMUL(FMUL(eps2, fabsf(dget(m - 1))), fabsf(dget(m - 2))), safmin)) goto L110;
        }
    }
    m = lend;
L110:
    if (m > lend) eset(m - 2, 0.f);
    p = dget(l - 1);
    if (m == l) goto L130;
    if (m == l - 1) {
        slaev2f(dget(l - 2), eget(l - 2), dget(l - 1), &rt1, &rt2, &c, &s);
        wcset(m - 1, c); wsset(m - 1, s);
        slasr_fL(l - 1, 2);
        dset(l - 2, rt1); dset(l - 1, rt2); eset(l - 2, 0.f);
        l -= 2;
        if (l >= lend) goto L90;
        goto L140;
    }
    if (jtot == nmaxit) goto L140;
    jtot++;
    g = FDIV(FSUB(dget(l - 2), p), FMUL(2.f, eget(l - 2)));
    r = slapy2f(g, 1.f);
    g = FADD(FSUB(dget(m - 1), p), FDIV(eget(l - 2), FADD(g, f_sign(r, g))));
    s = 1.f; c = 1.f; p = 0.f;
    for (i = m; i <= l - 1; ++i) {
        f  = FMUL(s, eget(i - 1));
        bb = FMUL(c, eget(i - 1));
        slartgf(g, f, &c, &s, &r);
        if (i != m) eset(i - 2, r);
        g = FSUB(dget(i - 1), p);
        r = FADD(FMUL(FSUB(dget(i), g), s), FMUL(FMUL(2.f, c), bb));
        p = FMUL(s, r);
        dset(i - 1, FADD(g, p));
        g = FSUB(FMUL(c, r), bb);
        wcset(i - 1, c); wsset(i - 1, s);
    }
    slasr_fL(m, l - m + 1);
    dset(l - 1, FSUB(dget(l - 1), p));
    eset(l - 2, g);
    goto L90;
L130:
    dset(l - 1, p);
    l--;
    if (l >= lend) goto L90;
    goto L140;

L140:
    if (jtot < nmaxit) goto L10;
    goto L160;

L160:
    {
        auto swapcol = [&](int c1, int c2) {
            float t;
            if (c1 == 0 && c2 == 1) {
                t = za0; za0 = zb0; zb0 = t;
                t = za1; za1 = zb1; zb1 = t;
                t = za2; za2 = zb2; zb2 = t;
            } else if (c1 == 0) {
                t = za0; za0 = zc0; zc0 = t;
                t = za1; za1 = zc1; zc1 = t;
                t = za2; za2 = zc2; zc2 = t;
            } else {
                t = zb0; zb0 = zc0; zc0 = t;
                t = zb1; zb1 = zc1; zc1 = t;
                t = zb2; zb2 = zc2; zc2 = t;
            }
        };
        for (int ii = 2; ii <= 3; ++ii) {
            int ia = ii - 1, k = ia;
            float pp = dget(ia - 1);
            for (int j = ii; j <= 3; ++j)
                if (dget(j - 1) < pp) { k = j; pp = dget(j - 1); }
            if (k != ia) {
                dset(k - 1, dget(ia - 1)); dset(ia - 1, pp);
                swapcol(ia - 1, k - 1);
            }
        }
    }
}

__device__ void smallest_eigvec3(float a11, float a21, float a31,
                                 float a22, float a32, float a33,
                                 float* nrm) {
    float alpha = a21;
    float xnorm = fabsf(a31);
    float tau1, v3, eh;
    if (xnorm == 0.f) {
        tau1 = 0.f; eh = alpha; v3 = 0.f;
    } else {
        float beta = -f_sign(slapy2f(alpha, xnorm), alpha);
        tau1 = FDIV(FSUB(beta, alpha), beta);
        v3   = FMUL(a31, FDIV(1.f, FSUB(alpha, beta)));
        eh   = beta;
    }
    if (tau1 != 0.f) {
        float x1 = FMUL(tau1, FADD(a22, FMUL(a32, v3)));
        float x2 = FMUL(tau1, FADD(a32, FMUL(a33, v3)));
        float al = FMUL(FMUL(-0.5f, tau1), FADD(x1, FMUL(x2, v3)));
        float w1 = FADD(x1, al);
        float w2 = FADD(x2, FMUL(al, v3));
        a22 = FSUB(a22, FMUL(2.f, w1));
        a32 = FSUB(a32, FADD(FMUL(v3, w1), w2));
        a33 = FSUB(a33, FMUL(2.f, FMUL(v3, w2)));
    }
    float d0 = a11, d1 = a22, d2 = a33;
    float e0 = eh, e1 = a32;
    float za0 = 1.f, za1 = 0.f, za2 = 0.f;
    float zb0 = 0.f, zb1 = 1.f, zb2 = 0.f;
    float zc0 = 0.f, zc1 = 0.f, zc2 = 1.f;

    ssteqr3_reg(d0, d1, d2, e0, e1,
                za0, za1, za2, zb0, zb1, zb2, zc0, zc1, zc2);

    float z0 = za0, z1 = za1, z2 = za2;
    if (tau1 != 0.f) {
        float t = FMUL(tau1, FADD(z1, FMUL(v3, z2)));
        z1 = FSUB(z1, t);
        z2 = FSUB(z2, FMUL(t, v3));
    }
    nrm[0] = z0; nrm[1] = z1; nrm[2] = z2;
}

// ---------------------------------------------------------------------------
// Kernel A: kNN with 2 warps per point. u64 keys (sq_bits<<32 | j) are unique,
// so any partition of the candidate set yields the identical top-11.
// Half-warps each build a sorted 11-list; cross-merge + covariance on half 0.
// ---------------------------------------------------------------------------
__global__ void __launch_bounds__(256)
knn_cov_kernel(const float* __restrict__ pts, float* __restrict__ cov) {
    __shared__ float sx[NPTS], sy[NPTS], sz[NPTS];
    __shared__ unsigned long long scand[4][2][11];
    int tid = threadIdx.x;
    for (int j = tid; j < NPTS; j += 256) {
        sx[j] = pts[j * 3 + 0];
        sy[j] = pts[j * 3 + 1];
        sz[j] = pts[j * 3 + 2];
    }
    __syncthreads();

    int warp = tid >> 5, lane = tid & 31;
    int wp   = warp >> 1;                 // point slot within block (0..3)
    int half = warp & 1;                  // candidate half
    int p    = blockIdx.x * 4 + wp;

    float pix = sx[p], piy = sy[p], piz = sz[p];

    unsigned long long kv[KNN + 1];
    #pragma unroll
    for (int q = 0; q <= KNN; ++q) kv[q] = 0xFFFFFFFFFFFFFFFFull;

    int base = half * (NPTS / 2);
    #pragma unroll 4
    for (int s = 0; s < NPTS / 64; ++s) {
        int j = base + s * 32 + lane;
        float dx = FSUB(pix, sx[j]);
        float dy = FSUB(piy, sy[j]);
        float dz = FSUB(piz, sz[j]);
        float sq = FADD(FADD(FMUL(dx, dx), FMUL(dy, dy)), FMUL(dz, dz));
        unsigned long long key =
            ((unsigned long long)__float_as_uint(sq) << 32) | (unsigned)j;
        if (key < kv[KNN]) {
            kv[KNN] = key;
            #pragma unroll
            for (int q = KNN; q > 0; --q) {
                unsigned long long a = kv[q - 1], b = kv[q];
                kv[q - 1] = (a < b) ? a : b;
                kv[q]     = (a < b) ? b : a;
            }
        }
    }

    // intra-warp merge: 11 rounds of warp-min over per-lane sorted heads
    #pragma unroll
    for (int r = 0; r <= KNN; ++r) {
        unsigned long long mykey = kv[0];
        unsigned long long m = mykey;
        #pragma unroll
        for (int off = 16; off > 0; off >>= 1) {
            unsigned long long o = __shfl_xor_sync(0xFFFFFFFFu, m, off);
            m = (o < m) ? o : m;
        }
        if (lane == r) scand[wp][half][r] = m;
        if (mykey == m) {
            #pragma unroll
            for (int q = 0; q < KNN; ++q) kv[q] = kv[q + 1];
            kv[KNN] = 0xFFFFFFFFFFFFFFFFull;
        }
    }
    __syncthreads();

    if (half == 0) {
        // cross-merge the two sorted 11-lists (22 unique keys)
        unsigned long long key = 0xFFFFFFFFFFFFFFFFull;
        if (lane < 11)       key = scand[wp][0][lane];
        else if (lane < 22)  key = scand[wp][1][lane - 11];

        int nbr[KNN + 1];
        #pragma unroll
        for (int r = 0; r <= KNN; ++r) {
            unsigned long long m = key;
            #pragma unroll
            for (int off = 16; off > 0; off >>= 1) {
                unsigned long long o = __shfl_xor_sync(0xFFFFFFFFu, m, off);
                m = (o < m) ? o : m;
            }
            nbr[r] = (int)(unsigned)(m & 0xFFFFFFFFull);
            if (key == m) key = 0xFFFFFFFFFFFFFFFFull;
        }

        if (lane == 0) {
            float nx[KNN], ny[KNN], nz[KNN];
            float mx = 0.f, my = 0.f, mz = 0.f;
            #pragma unroll
            for (int k = 0; k < KNN; ++k) {
                int j = nbr[k + 1];
                nx[k] = sx[j]; ny[k] = sy[j]; nz[k] = sz[j];
                mx = FADD(mx, nx[k]); my = FADD(my, ny[k]); mz = FADD(mz, nz[k]);
            }
            mx = FDIV(mx, 10.f); my = FDIV(my, 10.f); mz = FDIV(mz, 10.f);

            float c00 = 0.f, c10 = 0.f, c20 = 0.f, c11 = 0.f, c21 = 0.f, c22 = 0.f;
            #pragma unroll
            for (int k = 0; k < KNN; ++k) {
                float cx = FSUB(nx[k], mx);
                float cy = FSUB(ny[k], my);
                float cz = FSUB(nz[k], mz);
                c00 = FADD(c00, FMUL(cx, cx));
                c10 = FADD(c10, FMUL(cy, cx));
                c20 = FADD(c20, FMUL(cz, cx));
                c11 = FADD(c11, FMUL(cy, cy));
                c21 = FADD(c21, FMUL(cz, cy));
                c22 = FADD(c22, FMUL(cz, cz));
            }
            cov[0 * NPTS + p] = FDIV(c00, 10.f);
            cov[1 * NPTS + p] = FDIV(c10, 10.f);
            cov[2 * NPTS + p] = FDIV(c20, 10.f);
            cov[3 * NPTS + p] = FDIV(c11, 10.f);
            cov[4 * NPTS + p] = FDIV(c21, 10.f);
            cov[5 * NPTS + p] = FDIV(c22, 10.f);
        }
    }
}

// ---------------------------------------------------------------------------
// Kernel B: eigensolver, thread-per-point (full lane utilization)
// ---------------------------------------------------------------------------
__global__ void __launch_bounds__(32)
eigen_kernel(const float* __restrict__ pts, const float* __restrict__ cov,
             float* __restrict__ soa) {
    int i = blockIdx.x * 32 + threadIdx.x;
    float c00 = cov[0 * NPTS + i];
    float c10 = cov[1 * NPTS + i];
    float c20 = cov[2 * NPTS + i];
    float c11 = cov[3 * NPTS + i];
    float c21 = cov[4 * NPTS + i];
    float c22 = cov[5 * NPTS + i];

    float nrm[3];
    smallest_eigvec3(c00, c10, c20, c11, c21, c22, nrm);

    soa[i]            = pts[i * 3 + 0];
    soa[NPTS + i]     = pts[i * 3 + 1];
    soa[2 * NPTS + i] = pts[i * 3 + 2];
    soa[3 * NPTS + i] = nrm[0];
    soa[4 * NPTS + i] = nrm[1];
    soa[5 * NPTS + i] = nrm[2];
    soa[6 * NPTS + i] = nrm[0] * nrm[0] + nrm[1] * nrm[1] + nrm[2] * nrm[2];
}

// ---------------------------------------------------------------------------
// Fast atan2 for y >= 0 (result in [0, pi]); cephes coefficients, ~1e-7 abs err
// ---------------------------------------------------------------------------
__device__ __forceinline__ float fast_atan2_pos(float y, float x) {
    const float PI    = 3.14159265358979323846f;
    const float PIO2  = 1.57079632679489661923f;
    const float PIO4  = 0.78539816339744830962f;
    const float TAN8  = 0.41421356237309504880f;

    float ax = fabsf(x);
    float mn = fminf(y, ax), mx = fmaxf(y, ax);
    float t = (mx == 0.f) ? 0.f : __fdividef(mn, mx);

    float add = 0.f;
    if (t > TAN8) { t = __fdividef(t - 1.f, t + 1.f); add = PIO4; }

    float z = t * t;
    float p = 8.05374449538e-2f;
    p = p * z - 1.38776856032e-1f;
    p = p * z + 1.99777106478e-1f;
    p = p * z - 3.33329491539e-1f;
    float r = fmaf(p * z, t, t) + add;

    if (y > ax)  r = PIO2 - r;
    if (x < 0.f) r = PI - r;
    return r;
}

__device__ __forceinline__ void ppf_pair(
    float pix, float piy, float piz, float nix, float niy, float niz, float nis,
    float pjx, float pjy, float pjz, float njx, float njy, float njz, float njs,
    float& dn, float& a1, float& a2, float& a3)
{
    float dx = pix - pjx, dy = piy - pjy, dz = piz - pjz;
    float sq = dx * dx + dy * dy + dz * dz;
    dn = (sq > 0.f) ? sq * rsqrtf(sq) : 0.f;

    float dot1 = nix * dx + niy * dy + niz * dz;
    float csq1 = fmaf(nis, sq, -(dot1 * dot1));
    float cn1  = (csq1 > 0.f) ? csq1 * rsqrtf(csq1) : 0.f;
    a1 = fast_atan2_pos(cn1, dot1);

    float dot2 = njx * dx + njy * dy + njz * dz;
    float csq2 = fmaf(njs, sq, -(dot2 * dot2));
    float cn2  = (csq2 > 0.f) ? csq2 * rsqrtf(csq2) : 0.f;
    a2 = fast_atan2_pos(cn2, dot2);

    float dot3 = nix * njx + niy * njy + niz * njz;
    float csq3 = fmaf(nis, njs, -(dot3 * dot3));
    float cn3  = (csq3 > 0.f) ? csq3 * rsqrtf(csq3) : 0.f;
    a3 = fast_atan2_pos(cn3, dot3);
}

// ---------------------------------------------------------------------------
// Kernel C: symmetric PPF, 2 warps per unordered 32x32 tile pair (steps split).
// F(j,i) = [dn, pi - a2, pi - a1, a3] exactly. Single writer per part slot.
// ---------------------------------------------------------------------------
__global__ void __launch_bounds__(128)
sym_ppf_kernel(const float* __restrict__ soa, float4* __restrict__ part) {
    const float PI = 3.14159265358979323846f;
    int gw = blockIdx.x * 4 + (threadIdx.x >> 5);
    if (gw >= NTPAIRS * 2) return;
    int wt = gw >> 1;          // tile pair
    int sh = gw & 1;           // step half
    int lane = threadIdx.x & 31;

    // decode wt -> (A, B), 0 <= B <= A < 64, wt = A(A+1)/2 + B
    int A = (int)((sqrtf(8.f * (float)wt + 1.f) - 1.f) * 0.5f);
    while ((A + 1) * (A + 2) / 2 <= wt) ++A;
    while (A * (A + 1) / 2 > wt) --A;
    int B = wt - A * (A + 1) / 2;

    const float* px = soa;
    const float* py = soa + NPTS;
    const float* pz = soa + 2 * NPTS;
    const float* nx = soa + 3 * NPTS;
    const float* ny = soa + 4 * NPTS;
    const float* nz = soa + 5 * NPTS;
    const float* ns = soa + 6 * NPTS;

    int ri = B * 32 + lane;
    int rj = A * 32 + lane;
    float pix = __ldg(&px[ri]), piy = __ldg(&py[ri]), piz = __ldg(&pz[ri]);
    float nix = __ldg(&nx[ri]), niy = __ldg(&ny[ri]), niz = __ldg(&nz[ri]);
    float nis = __ldg(&ns[ri]);
    float qjx = __ldg(&px[rj]), qjy = __ldg(&py[rj]), qjz = __ldg(&pz[rj]);
    float mjx = __ldg(&nx[rj]), mjy = __ldg(&ny[rj]), mjz = __ldg(&nz[rj]);
    float mjs = __ldg(&ns[rj]);

    float ai0 = 0.f, ai1 = 0.f, ai2 = 0.f, ai3 = 0.f;
    float aj0 = 0.f, aj1 = 0.f, aj2 = 0.f, aj3 = 0.f;
    int s0i = sh * 16;

    if (A != B) {
        #pragma unroll 4
        for (int s = s0i; s < s0i + 16; ++s) {
            int src = (lane + s) & 31;
            float pjx = __shfl_sync(0xFFFFFFFFu, qjx, src);
            float pjy = __shfl_sync(0xFFFFFFFFu, qjy, src);
            float pjz = __shfl_sync(0xFFFFFFFFu, qjz, src);
            float njx = __shfl_sync(0xFFFFFFFFu, mjx, src);
            float njy = __shfl_sync(0xFFFFFFFFu, mjy, src);
            float njz = __shfl_sync(0xFFFFFFFFu, mjz, src);
            float njs = __shfl_sync(0xFFFFFFFFu, mjs, src);

            float dn, a1, a2, a3;
            ppf_pair(pix, piy, piz, nix, niy, niz, nis,
                     pjx, pjy, pjz, njx, njy, njz, njs, dn, a1, a2, a3);

            ai0 += dn; ai1 += a1; ai2 += a2; ai3 += a3;

            float c0 = dn, c1 = PI - a2, c2 = PI - a1, c3 = a3;
            int rsrc = (lane - s) & 31;
            aj0 += __shfl_sync(0xFFFFFFFFu, c0, rsrc);
            aj1 += __shfl_sync(0xFFFFFFFFu, c1, rsrc);
            aj2 += __shfl_sync(0xFFFFFFFFu, c2, rsrc);
            aj3 += __shfl_sync(0xFFFFFFFFu, c3, rsrc);
        }
        part[ri * NCOLS + 2 * A + sh] = make_float4(ai0, ai1, ai2, ai3);
        part[rj * NCOLS + 2 * B + sh] = make_float4(aj0, aj1, aj2, aj3);
    } else {
        #pragma unroll 4
        for (int s = s0i; s < s0i + 16; ++s) {
            int src = (lane + s) & 31;
            float pjx = __shfl_sync(0xFFFFFFFFu, qjx, src);
            float pjy = __shfl_sync(0xFFFFFFFFu, qjy, src);
            float pjz = __shfl_sync(0xFFFFFFFFu, qjz, src);
            float njx = __shfl_sync(0xFFFFFFFFu, mjx, src);
            float njy = __shfl_sync(0xFFFFFFFFu, mjy, src);
            float njz = __shfl_sync(0xFFFFFFFFu, mjz, src);
            float njs = __shfl_sync(0xFFFFFFFFu, mjs, src);

            float dn, a1, a2, a3;
            ppf_pair(pix, piy, piz, nix, niy, niz, nis,
                     pjx, pjy, pjz, njx, njy, njz, njs, dn, a1, a2, a3);

            ai0 += dn; ai1 += a1; ai2 += a2; ai3 += a3;
        }
        part[ri * NCOLS + 2 * A + sh] = make_float4(ai0, ai1, ai2, ai3);
    }
}

// ---------------------------------------------------------------------------
// Kernel D: reduce 128 partials per row (fixed order) + 4->256 linear layer
// ---------------------------------------------------------------------------
__global__ void __launch_bounds__(256)
finalize_kernel(const float4* __restrict__ part,
                const float* __restrict__ W, const float* __restrict__ b,
                float* __restrict__ out) {
    __shared__ float4 sf[NCOLS];
    __shared__ float feat[4];
    int i = blockIdx.x, t = threadIdx.x;
    if (t < NCOLS) sf[t] = part[i * NCOLS + t];
    __syncthreads();
    if (t == 0) {
        float s0 = 0.f, s1 = 0.f, s2 = 0.f, s3 = 0.f;
        #pragma unroll
        for (int q = 0; q < NCOLS; ++q) {
            float4 v = sf[q];
            s0 += v.x; s1 += v.y; s2 += v.z; s3 += v.w;
        }
        feat[0] = s0 / 2048.f; feat[1] = s1 / 2048.f;
        feat[2] = s2 / 2048.f; feat[3] = s3 / 2048.f;
    }
    __syncthreads();
    float f0 = feat[0], f1 = feat[1], f2 = feat[2], f3 = feat[3];
    float acc = f0 * W[t * 4 + 0];
    acc = acc + f1 * W[t * 4 + 1];
    acc = acc + f2 * W[t * 4 + 2];
    acc = acc + f3 * W[t * 4 + 3];
    acc = acc + b[t];
    out[i * OUTF + t] = acc;
}

extern "C" void kernel_launch(void* const* d_in, const int* in_sizes, int n_in,
                              void* d_out, int out_size) {
    const float* points = (const float*)d_in[0];   // (1, 2048, 3)
    const float* W      = (const float*)d_in[1];   // (256, 4)
    const float* b      = (const float*)d_in[2];   // (256,)
    float* out          = (float*)d_out;           // (1, 2048, 256)
    (void)in_sizes; (void)n_in; (void)out_size;

    float* soa; float* cov; float4* part;
    cudaGetSymbolAddress((void**)&soa, g_soa);
    cudaGetSymbolAddress((void**)&cov, g_cov);
    cudaGetSymbolAddress((void**)&part, g_part);

    knn_cov_kernel<<<NPTS / 4, 256>>>(points, cov);
    eigen_kernel<<<NPTS / 32, 32>>>(points, cov, soa);
    sym_ppf_kernel<<<(NTPAIRS * 2 + 3) / 4, 128>>>(soa, part);
    finalize_kernel<<<NPTS, 256>>>(part, W, b, out);
}

// round 12
// speedup vs baseline: 1.1017x; 1.1017x over previous
#include <cuda_runtime.h>
#include <cuda_bf16.h>
#include <math.h>
#include <float.h>

#define NPTS 2048
#define KNN  10
#define OUTF 256
#define NTILES 64                 // 2048 / 32
#define NTPAIRS 2080              // 64*65/2

// _rn intrinsics: immune to compiler fast-math; used on all eigen/kNN-critical math
#define FMUL(a,b)  __fmul_rn((a),(b))
#define FADD(a,b)  __fadd_rn((a),(b))
#define FSUB(a,b)  __fsub_rn((a),(b))
#define FDIV(a,b)  __fdiv_rn((a),(b))
#define FSQRT(a)   __fsqrt_rn((a))

// SoA: [0..N)=px [N..2N)=py [2N..3N)=pz [3N..4N)=nx [4N..5N)=ny [5N..6N)=nz [6N..7N)=|n|^2
__device__ float  g_soa[NPTS * 7];
// covariance scratch, SoA: 6 slices of NPTS
__device__ float  g_cov[NPTS * 6];
// per-(row, col-tile) partial PPF sums; single writer per slot (deterministic)
__device__ float4 g_part[NPTS * NTILES];

// ---------------------------------------------------------------------------
// LAPACK fp32 building blocks (netlib-faithful, LAPACK >= 3.10 conventions)
// ---------------------------------------------------------------------------

__device__ __forceinline__ float f_sign(float a, float b) {
    return (b >= 0.f) ? fabsf(a) : -fabsf(a);
}

__device__ __forceinline__ float slapy2f(float x, float y) {
    float xa = fabsf(x), ya = fabsf(y);
    float w = fmaxf(xa, ya), z = fminf(xa, ya);
    if (z == 0.f) return w;
    float t = FDIV(z, w);
    return FMUL(w, FSQRT(FADD(1.f, FMUL(t, t))));
}

__device__ __forceinline__ void slartgf(float f, float g, float* c, float* s, float* r) {
    if (g == 0.f)      { *c = 1.f; *s = 0.f; *r = f; }
    else if (f == 0.f) { *c = 0.f; *s = (g >= 0.f) ? 1.f : -1.f; *r = fabsf(g); }
    else {
        float d  = FSQRT(FADD(FMUL(f, f), FMUL(g, g)));
        float rr = (f >= 0.f) ? d : -d;
        *c = FDIV(fabsf(f), d);
        *s = FDIV(g, rr);
        *r = rr;
    }
}

__device__ void slaev2f(float a, float b, float c,
                        float* rt1, float* rt2, float* cs1, float* sn1) {
    float sm  = FADD(a, c);
    float df  = FSUB(a, c);
    float adf = fabsf(df);
    float tb  = FADD(b, b);
    float ab  = fabsf(tb);
    float acmx, acmn;
    if (fabsf(a) > fabsf(c)) { acmx = a; acmn = c; } else { acmx = c; acmn = a; }
    float rt;
    if (adf > ab) {
        float t = FDIV(ab, adf);
        rt = FMUL(adf, FSQRT(FADD(1.f, FMUL(t, t))));
    } else if (adf < ab) {
        float t = FDIV(adf, ab);
        rt = FMUL(ab, FSQRT(FADD(1.f, FMUL(t, t))));
    } else {
        rt = FMUL(ab, FSQRT(2.f));
    }
    int sgn1;
    if (sm < 0.f) {
        *rt1 = FMUL(0.5f, FSUB(sm, rt)); sgn1 = -1;
        *rt2 = FSUB(FMUL(FDIV(acmx, *rt1), acmn), FMUL(FDIV(b, *rt1), b));
    } else if (sm > 0.f) {
        *rt1 = FMUL(0.5f, FADD(sm, rt)); sgn1 = 1;
        *rt2 = FSUB(FMUL(FDIV(acmx, *rt1), acmn), FMUL(FDIV(b, *rt1), b));
    } else {
        *rt1 = FMUL(0.5f, rt); *rt2 = FMUL(-0.5f, rt); sgn1 = 1;
    }
    float cs; int sgn2;
    if (df >= 0.f) { cs = FADD(df, rt); sgn2 =  1; }
    else           { cs = FSUB(df, rt); sgn2 = -1; }
    float acs = fabsf(cs);
    if (acs > ab) {
        float ct = FDIV(-tb, cs);
        *sn1 = FDIV(1.f, FSQRT(FADD(1.f, FMUL(ct, ct))));
        *cs1 = FMUL(ct, *sn1);
    } else {
        if (ab == 0.f) { *cs1 = 1.f; *sn1 = 0.f; }
        else {
            float tn = FDIV(-cs, tb);
            *cs1 = FDIV(1.f, FSQRT(FADD(1.f, FMUL(tn, tn))));
            *sn1 = FMUL(tn, *cs1);
        }
    }
    if (sgn1 == sgn2) { float tn = *cs1; *cs1 = -(*sn1); *sn1 = tn; }
}

// ssteqr('I', n=3), register-resident; control flow/arithmetic == netlib
__device__ void ssteqr3_reg(float& d0, float& d1, float& d2,
                            float& e0, float& e1,
                            float& za0, float& za1, float& za2,
                            float& zb0, float& zb1, float& zb2,
                            float& zc0, float& zc1, float& zc2) {
    const float eps    = 5.9604645e-8f;
    const float eps2   = eps * eps;
    const float safmin = 1.17549435e-38f;
    float wc0 = 0.f, wc1 = 0.f, ws0 = 0.f, ws1 = 0.f;

    auto dget = [&](int i) -> float { return i == 0 ? d0 : (i == 1 ? d1 : d2); };
    auto dset = [&](int i, float v) { if (i == 0) d0 = v; else if (i == 1) d1 = v; else d2 = v; };
    auto eget = [&](int i) -> float { return i == 0 ? e0 : e1; };
    auto eset = [&](int i, float v) { if (i == 0) e0 = v; else e1 = v; };
    auto wcget = [&](int i) -> float { return i == 0 ? wc0 : wc1; };
    auto wcset = [&](int i, float v) { if (i == 0) wc0 = v; else wc1 = v; };
    auto wsget = [&](int i) -> float { return i == 0 ? ws0 : ws1; };
    auto wsset = [&](int i, float v) { if (i == 0) ws0 = v; else ws1 = v; };

    auto rot = [&](int cb1, float c, float s) {
        if (cb1 == 1) {
            float t;
            t = zb0; zb0 = FSUB(FMUL(c, t), FMUL(s, za0)); za0 = FADD(FMUL(s, t), FMUL(c, za0));
            t = zb1; zb1 = FSUB(FMUL(c, t), FMUL(s, za1)); za1 = FADD(FMUL(s, t), FMUL(c, za1));
            t = zb2; zb2 = FSUB(FMUL(c, t), FMUL(s, za2)); za2 = FADD(FMUL(s, t), FMUL(c, za2));
        } else {
            float t;
            t = zc0; zc0 = FSUB(FMUL(c, t), FMUL(s, zb0)); zb0 = FADD(FMUL(s, t), FMUL(c, zb0));
            t = zc1; zc1 = FSUB(FMUL(c, t), FMUL(s, zb1)); zb1 = FADD(FMUL(s, t), FMUL(c, zb1));
            t = zc2; zc2 = FSUB(FMUL(c, t), FMUL(s, zb2)); zb2 = FADD(FMUL(s, t), FMUL(c, zb2));
        }
    };
    auto slasr_bL = [&](int lcol, int mm) {
        for (int j = mm - 1; j >= 1; --j) {
            float c = wcget(lcol - 2 + j), s = wsget(lcol - 2 + j);
            if (c != 1.f || s != 0.f) rot(lcol + j - 1, c, s);
        }
    };
    auto slasr_fL = [&](int lcol, int mm) {
        for (int j = 1; j <= mm - 1; ++j) {
            float c = wcget(lcol - 2 + j), s = wsget(lcol - 2 + j);
            if (c != 1.f || s != 0.f) rot(lcol + j - 1, c, s);
        }
    };

    int l1, l, lsv, lend, lendsv, m, i, jtot, nmaxit;
    float p, g, r, s, c, f, bb, rt1, rt2, anorm, tst;
    nmaxit = 90; jtot = 0; l1 = 1;

L10:
    if (l1 > 3) goto L160;
    if (l1 > 1) eset(l1 - 2, 0.f);
    if (l1 <= 2) {
        for (m = l1; m <= 2; ++m) {
            tst = fabsf(eget(m - 1));
            if (tst == 0.f) goto L30;
            if (tst <= FMUL(FMUL(FSQRT(fabsf(dget(m - 1))), FSQRT(fabsf(dget(m)))), eps)) {
                eset(m - 1, 0.f); goto L30;
            }
        }
    }
    m = 3;
L30:
    l = l1; lsv = l; lend = m; lendsv = lend; l1 = m + 1;
    if (lend == l) goto L10;
    anorm = 0.f;
    for (i = l; i <= lend; ++i)     anorm = fmaxf(anorm, fabsf(dget(i - 1)));
    for (i = l; i <= lend - 1; ++i) anorm = fmaxf(anorm, fabsf(eget(i - 1)));
    if (anorm == 0.f) goto L10;
    if (fabsf(dget(lend - 1)) < fabsf(dget(l - 1))) { lend = lsv; l = lendsv; }
    if (lend > l) goto L40; else goto L90;

L40: // QL
    if (l != lend) {
        for (m = l; m <= lend - 1; ++m) {
            tst = FMUL(eget(m - 1), eget(m - 1));
            if (tst <= FADD(FMUL(FMUL(eps2, fabsf(dget(m - 1))), fabsf(dget(m))), safmin)) goto L60;
        }
    }
    m = lend;
L60:
    if (m < lend) eset(m - 1, 0.f);
    p = dget(l - 1);
    if (m == l) goto L80;
    if (m == l + 1) {
        slaev2f(dget(l - 1), eget(l - 1), dget(l), &rt1, &rt2, &c, &s);
        wcset(l - 1, c); wsset(l - 1, s);
        slasr_bL(l, 2);
        dset(l - 1, rt1); dset(l, rt2); eset(l - 1, 0.f);
        l += 2;
        if (l <= lend) goto L40;
        goto L140;
    }
    if (jtot == nmaxit) goto L140;
    jtot++;
    g = FDIV(FSUB(dget(l), p), FMUL(2.f, eget(l - 1)));
    r = slapy2f(g, 1.f);
    g = FADD(FSUB(dget(m - 1), p), FDIV(eget(l - 1), FADD(g, f_sign(r, g))));
    s = 1.f; c = 1.f; p = 0.f;
    for (i = m - 1; i >= l; --i) {
        f  = FMUL(s, eget(i - 1));
        bb = FMUL(c, eget(i - 1));
        slartgf(g, f, &c, &s, &r);
        if (i != m - 1) eset(i, r);
        g = FSUB(dget(i), p);
        r = FADD(FMUL(FSUB(dget(i - 1), g), s), FMUL(FMUL(2.f, c), bb));
        p = FMUL(s, r);
        dset(i, FADD(g, p));
        g = FSUB(FMUL(c, r), bb);
        wcset(i - 1, c); wsset(i - 1, -s);
    }
    slasr_bL(l, m - l + 1);
    dset(l - 1, FSUB(dget(l - 1), p));
    eset(l - 1, g);
    goto L40;
L80:
    dset(l - 1, p);
    l++;
    if (l <= lend) goto L40;
    goto L140;

L90: // QR
    if (l != lend) {
        for (m = l; m >= lend + 1; --m) {
            tst = FMUL(eget(m - 2), eget(m - 2));
            if (tst <= FADD(FMUL(FMUL(eps2, fabsf(dget(m - 1))), fabsf(dget(m - 2))), safmin)) goto L110;
        }
    }
    m = lend;
L110:
    if (m > lend) eset(m - 2, 0.f);
    p = dget(l - 1);
    if (m == l) goto L130;
    if (m == l - 1) {
        slaev2f(dget(l - 2), eget(l - 2), dget(l - 1), &rt1, &rt2, &c, &s);
        wcset(m - 1, c); wsset(m - 1, s);
        slasr_fL(l - 1, 2);
        dset(l - 2, rt1); dset(l - 1, rt2); eset(l - 2, 0.f);
        l -= 2;
        if (l >= lend) goto L90;
        goto L140;
    }
    if (jtot == nmaxit) goto L140;
    jtot++;
    g = FDIV(FSUB(dget(l - 2), p), FMUL(2.f, eget(l - 2)));
    r = slapy2f(g, 1.f);
    g = FADD(FSUB(dget(m - 1), p), FDIV(eget(l - 2), FADD(g, f_sign(r, g))));
    s = 1.f; c = 1.f; p = 0.f;
    for (i = m; i <= l - 1; ++i) {
        f  = FMUL(s, eget(i - 1));
        bb = FMUL(c, eget(i - 1));
        slartgf(g, f, &c, &s, &r);
        if (i != m) eset(i - 2, r);
        g = FSUB(dget(i - 1), p);
        r = FADD(FMUL(FSUB(dget(i), g), s), FMUL(FMUL(2.f, c), bb));
        p = FMUL(s, r);
        dset(i - 1, FADD(g, p));
        g = FSUB(FMUL(c, r), bb);
        wcset(i - 1, c); wsset(i - 1, s);
    }
    slasr_fL(m, l - m + 1);
    dset(l - 1, FSUB(dget(l - 1), p));
    eset(l - 2, g);
    goto L90;
L130:
    dset(l - 1, p);
    l--;
    if (l >= lend) goto L90;
    goto L140;

L140:
    if (jtot < nmaxit) goto L10;
    goto L160;

L160:
    {
        auto swapcol = [&](int c1, int c2) {
            float t;
            if (c1 == 0 && c2 == 1) {
                t = za0; za0 = zb0; zb0 = t;
                t = za1; za1 = zb1; zb1 = t;
                t = za2; za2 = zb2; zb2 = t;
            } else if (c1 == 0) {
                t = za0; za0 = zc0; zc0 = t;
                t = za1; za1 = zc1; zc1 = t;
                t = za2; za2 = zc2; zc2 = t;
            } else {
                t = zb0; zb0 = zc0; zc0 = t;
                t = zb1; zb1 = zc1; zc1 = t;
                t = zb2; zb2 = zc2; zc2 = t;
            }
        };
        for (int ii = 2; ii <= 3; ++ii) {
            int ia = ii - 1, k = ia;
            float pp = dget(ia - 1);
            for (int j = ii; j <= 3; ++j)
                if (dget(j - 1) < pp) { k = j; pp = dget(j - 1); }
            if (k != ia) {
                dset(k - 1, dget(ia - 1)); dset(ia - 1, pp);
                swapcol(ia - 1, k - 1);
            }
        }
    }
}

__device__ void smallest_eigvec3(float a11, float a21, float a31,
                                 float a22, float a32, float a33,
                                 float* nrm) {
    float alpha = a21;
    float xnorm = fabsf(a31);
    float tau1, v3, eh;
    if (xnorm == 0.f) {
        tau1 = 0.f; eh = alpha; v3 = 0.f;
    } else {
        float beta = -f_sign(slapy2f(alpha, xnorm), alpha);
        tau1 = FDIV(FSUB(beta, alpha), beta);
        v3   = FMUL(a31, FDIV(1.f, FSUB(alpha, beta)));
        eh   = beta;
    }
    if (tau1 != 0.f) {
        float x1 = FMUL(tau1, FADD(a22, FMUL(a32, v3)));
        float x2 = FMUL(tau1, FADD(a32, FMUL(a33, v3)));
        float al = FMUL(FMUL(-0.5f, tau1), FADD(x1, FMUL(x2, v3)));
        float w1 = FADD(x1, al);
        float w2 = FADD(x2, FMUL(al, v3));
        a22 = FSUB(a22, FMUL(2.f, w1));
        a32 = FSUB(a32, FADD(FMUL(v3, w1), w2));
        a33 = FSUB(a33, FMUL(2.f, FMUL(v3, w2)));
    }
    float d0 = a11, d1 = a22, d2 = a33;
    float e0 = eh, e1 = a32;
    float za0 = 1.f, za1 = 0.f, za2 = 0.f;
    float zb0 = 0.f, zb1 = 1.f, zb2 = 0.f;
    float zc0 = 0.f, zc1 = 0.f, zc2 = 1.f;

    ssteqr3_reg(d0, d1, d2, e0, e1,
                za0, za1, za2, zb0, zb1, zb2, zc0, zc1, zc2);

    float z0 = za0, z1 = za1, z2 = za2;
    if (tau1 != 0.f) {
        float t = FMUL(tau1, FADD(z1, FMUL(v3, z2)));
        z1 = FSUB(z1, t);
        z2 = FSUB(z2, FMUL(t, v3));
    }
    nrm[0] = z0; nrm[1] = z1; nrm[2] = z2;
}

// ---------------------------------------------------------------------------
// Kernel A: kNN with 2 warps per point. u64 keys (sq_bits<<32 | j) are unique,
// so any partition of the candidate set yields the identical top-11.
// ---------------------------------------------------------------------------
__global__ void __launch_bounds__(256)
knn_cov_kernel(const float* __restrict__ pts, float* __restrict__ cov) {
    __shared__ float sx[NPTS], sy[NPTS], sz[NPTS];
    __shared__ unsigned long long scand[4][2][11];
    int tid = threadIdx.x;
    for (int j = tid; j < NPTS; j += 256) {
        sx[j] = pts[j * 3 + 0];
        sy[j] = pts[j * 3 + 1];
        sz[j] = pts[j * 3 + 2];
    }
    __syncthreads();

    int warp = tid >> 5, lane = tid & 31;
    int wp   = warp >> 1;
    int half = warp & 1;
    int p    = blockIdx.x * 4 + wp;

    float pix = sx[p], piy = sy[p], piz = sz[p];

    unsigned long long kv[KNN + 1];
    #pragma unroll
    for (int q = 0; q <= KNN; ++q) kv[q] = 0xFFFFFFFFFFFFFFFFull;

    int base = half * (NPTS / 2);
    #pragma unroll 4
    for (int s = 0; s < NPTS / 64; ++s) {
        int j = base + s * 32 + lane;
        float dx = FSUB(pix, sx[j]);
        float dy = FSUB(piy, sy[j]);
        float dz = FSUB(piz, sz[j]);
        float sq = FADD(FADD(FMUL(dx, dx), FMUL(dy, dy)), FMUL(dz, dz));
        unsigned long long key =
            ((unsigned long long)__float_as_uint(sq) << 32) | (unsigned)j;
        if (key < kv[KNN]) {
            kv[KNN] = key;
            #pragma unroll
            for (int q = KNN; q > 0; --q) {
                unsigned long long a = kv[q - 1], b = kv[q];
                kv[q - 1] = (a < b) ? a : b;
                kv[q]     = (a < b) ? b : a;
            }
        }
    }

    #pragma unroll
    for (int r = 0; r <= KNN; ++r) {
        unsigned long long mykey = kv[0];
        unsigned long long m = mykey;
        #pragma unroll
        for (int off = 16; off > 0; off >>= 1) {
            unsigned long long o = __shfl_xor_sync(0xFFFFFFFFu, m, off);
            m = (o < m) ? o : m;
        }
        if (lane == r) scand[wp][half][r] = m;
        if (mykey == m) {
            #pragma unroll
            for (int q = 0; q < KNN; ++q) kv[q] = kv[q + 1];
            kv[KNN] = 0xFFFFFFFFFFFFFFFFull;
        }
    }
    __syncthreads();

    if (half == 0) {
        unsigned long long key = 0xFFFFFFFFFFFFFFFFull;
        if (lane < 11)       key = scand[wp][0][lane];
        else if (lane < 22)  key = scand[wp][1][lane - 11];

        int nbr[KNN + 1];
        #pragma unroll
        for (int r = 0; r <= KNN; ++r) {
            unsigned long long m = key;
            #pragma unroll
            for (int off = 16; off > 0; off >>= 1) {
                unsigned long long o = __shfl_xor_sync(0xFFFFFFFFu, m, off);
                m = (o < m) ? o : m;
            }
            nbr[r] = (int)(unsigned)(m & 0xFFFFFFFFull);
            if (key == m) key = 0xFFFFFFFFFFFFFFFFull;
        }

        if (lane == 0) {
            float nx[KNN], ny[KNN], nz[KNN];
            float mx = 0.f, my = 0.f, mz = 0.f;
            #pragma unroll
            for (int k = 0; k < KNN; ++k) {
                int j = nbr[k + 1];
                nx[k] = sx[j]; ny[k] = sy[j]; nz[k] = sz[j];
                mx = FADD(mx, nx[k]); my = FADD(my, ny[k]); mz = FADD(mz, nz[k]);
            }
            mx = FDIV(mx, 10.f); my = FDIV(my, 10.f); mz = FDIV(mz, 10.f);

            float c00 = 0.f, c10 = 0.f, c20 = 0.f, c11 = 0.f, c21 = 0.f, c22 = 0.f;
            #pragma unroll
            for (int k = 0; k < KNN; ++k) {
                float cx = FSUB(nx[k], mx);
                float cy = FSUB(ny[k], my);
                float cz = FSUB(nz[k], mz);
                c00 = FADD(c00, FMUL(cx, cx));
                c10 = FADD(c10, FMUL(cy, cx));
                c20 = FADD(c20, FMUL(cz, cx));
                c11 = FADD(c11, FMUL(cy, cy));
                c21 = FADD(c21, FMUL(cz, cy));
                c22 = FADD(c22, FMUL(cz, cz));
            }
            cov[0 * NPTS + p] = FDIV(c00, 10.f);
            cov[1 * NPTS + p] = FDIV(c10, 10.f);
            cov[2 * NPTS + p] = FDIV(c20, 10.f);
            cov[3 * NPTS + p] = FDIV(c11, 10.f);
            cov[4 * NPTS + p] = FDIV(c21, 10.f);
            cov[5 * NPTS + p] = FDIV(c22, 10.f);
        }
    }
}

// ---------------------------------------------------------------------------
// Kernel B: eigensolver, WARP-per-point, all 32 lanes redundantly compute the
// SAME point => every branch is warp-uniform (zero divergence). Lane 0 writes.
// ---------------------------------------------------------------------------
__global__ void __launch_bounds__(256)
eigen_kernel(const float* __restrict__ pts, const float* __restrict__ cov,
             float* __restrict__ soa) {
    int warp = threadIdx.x >> 5, lane = threadIdx.x & 31;
    int i = blockIdx.x * 8 + warp;

    float c00 = cov[0 * NPTS + i];
    float c10 = cov[1 * NPTS + i];
    float c20 = cov[2 * NPTS + i];
    float c11 = cov[3 * NPTS + i];
    float c21 = cov[4 * NPTS + i];
    float c22 = cov[5 * NPTS + i];

    float nrm[3];
    smallest_eigvec3(c00, c10, c20, c11, c21, c22, nrm);

    if (lane == 0) {
        soa[i]            = pts[i * 3 + 0];
        soa[NPTS + i]     = pts[i * 3 + 1];
        soa[2 * NPTS + i] = pts[i * 3 + 2];
        soa[3 * NPTS + i] = nrm[0];
        soa[4 * NPTS + i] = nrm[1];
        soa[5 * NPTS + i] = nrm[2];
        soa[6 * NPTS + i] = nrm[0] * nrm[0] + nrm[1] * nrm[1] + nrm[2] * nrm[2];
    }
}

// ---------------------------------------------------------------------------
// Fast atan2 for y >= 0 (result in [0, pi]); cephes coefficients, ~1e-7 abs err
// ---------------------------------------------------------------------------
__device__ __forceinline__ float fast_atan2_pos(float y, float x) {
    const float PI    = 3.14159265358979323846f;
    const float PIO2  = 1.57079632679489661923f;
    const float PIO4  = 0.78539816339744830962f;
    const float TAN8  = 0.41421356237309504880f;

    float ax = fabsf(x);
    float mn = fminf(y, ax), mx = fmaxf(y, ax);
    float t = (mx == 0.f) ? 0.f : __fdividef(mn, mx);

    float add = 0.f;
    if (t > TAN8) { t = __fdividef(t - 1.f, t + 1.f); add = PIO4; }

    float z = t * t;
    float p = 8.05374449538e-2f;
    p = p * z - 1.38776856032e-1f;
    p = p * z + 1.99777106478e-1f;
    p = p * z - 3.33329491539e-1f;
    float r = fmaf(p * z, t, t) + add;

    if (y > ax)  r = PIO2 - r;
    if (x < 0.f) r = PI - r;
    return r;
}

__device__ __forceinline__ void ppf_pair(
    float pix, float piy, float piz, float nix, float niy, float niz, float nis,
    float pjx, float pjy, float pjz, float njx, float njy, float njz, float njs,
    float& dn, float& a1, float& a2, float& a3)
{
    float dx = pix - pjx, dy = piy - pjy, dz = piz - pjz;
    float sq = dx * dx + dy * dy + dz * dz;
    dn = (sq > 0.f) ? sq * rsqrtf(sq) : 0.f;

    float dot1 = nix * dx + niy * dy + niz * dz;
    float csq1 = fmaf(nis, sq, -(dot1 * dot1));
    float cn1  = (csq1 > 0.f) ? csq1 * rsqrtf(csq1) : 0.f;
    a1 = fast_atan2_pos(cn1, dot1);

    float dot2 = njx * dx + njy * dy + njz * dz;
    float csq2 = fmaf(njs, sq, -(dot2 * dot2));
    float cn2  = (csq2 > 0.f) ? csq2 * rsqrtf(csq2) : 0.f;
    a2 = fast_atan2_pos(cn2, dot2);

    float dot3 = nix * njx + niy * njy + niz * njz;
    float csq3 = fmaf(nis, njs, -(dot3 * dot3));
    float cn3  = (csq3 > 0.f) ? csq3 * rsqrtf(csq3) : 0.f;
    a3 = fast_atan2_pos(cn3, dot3);
}

// ---------------------------------------------------------------------------
// Kernel C: symmetric PPF. One warp per unordered 32x32 tile pair (B <= A).
// F(j,i) = [dn, pi - a2(i,j), pi - a1(i,j), a3] (exact). Single writer/slot.
// ---------------------------------------------------------------------------
__global__ void __launch_bounds__(128)
sym_ppf_kernel(const float* __restrict__ soa, float4* __restrict__ part) {
    const float PI = 3.14159265358979323846f;
    int wt = blockIdx.x * 4 + (threadIdx.x >> 5);
    if (wt >= NTPAIRS) return;
    int lane = threadIdx.x & 31;

    int A = (int)((sqrtf(8.f * (float)wt + 1.f) - 1.f) * 0.5f);
    while ((A + 1) * (A + 2) / 2 <= wt) ++A;
    while (A * (A + 1) / 2 > wt) --A;
    int B = wt - A * (A + 1) / 2;

    const float* px = soa;
    const float* py = soa + NPTS;
    const float* pz = soa + 2 * NPTS;
    const float* nx = soa + 3 * NPTS;
    const float* ny = soa + 4 * NPTS;
    const float* nz = soa + 5 * NPTS;
    const float* ns = soa + 6 * NPTS;

    int ri = B * 32 + lane;
    int rj = A * 32 + lane;
    float pix = __ldg(&px[ri]), piy = __ldg(&py[ri]), piz = __ldg(&pz[ri]);
    float nix = __ldg(&nx[ri]), niy = __ldg(&ny[ri]), niz = __ldg(&nz[ri]);
    float nis = __ldg(&ns[ri]);
    float qjx = __ldg(&px[rj]), qjy = __ldg(&py[rj]), qjz = __ldg(&pz[rj]);
    float mjx = __ldg(&nx[rj]), mjy = __ldg(&ny[rj]), mjz = __ldg(&nz[rj]);
    float mjs = __ldg(&ns[rj]);

    float ai0 = 0.f, ai1 = 0.f, ai2 = 0.f, ai3 = 0.f;
    float aj0 = 0.f, aj1 = 0.f, aj2 = 0.f, aj3 = 0.f;

    if (A != B) {
        #pragma unroll 4
        for (int s = 0; s < 32; ++s) {
            int src = (lane + s) & 31;
            float pjx = __shfl_sync(0xFFFFFFFFu, qjx, src);
            float pjy = __shfl_sync(0xFFFFFFFFu, qjy, src);
            float pjz = __shfl_sync(0xFFFFFFFFu, qjz, src);
            float njx = __shfl_sync(0xFFFFFFFFu, mjx, src);
            float njy = __shfl_sync(0xFFFFFFFFu, mjy, src);
            float njz = __shfl_sync(0xFFFFFFFFu, mjz, src);
            float njs = __shfl_sync(0xFFFFFFFFu, mjs, src);

            float dn, a1, a2, a3;
            ppf_pair(pix, piy, piz, nix, niy, niz, nis,
                     pjx, pjy, pjz, njx, njy, njz, njs, dn, a1, a2, a3);

            ai0 += dn; ai1 += a1; ai2 += a2; ai3 += a3;

            float c0 = dn, c1 = PI - a2, c2 = PI - a1, c3 = a3;
            int rsrc = (lane - s) & 31;
            aj0 += __shfl_sync(0xFFFFFFFFu, c0, rsrc);
            aj1 += __shfl_sync(0xFFFFFFFFu, c1, rsrc);
            aj2 += __shfl_sync(0xFFFFFFFFu, c2, rsrc);
            aj3 += __shfl_sync(0xFFFFFFFFu, c3, rsrc);
        }
        part[ri * NTILES + A] = make_float4(ai0, ai1, ai2, ai3);
        part[rj * NTILES + B] = make_float4(aj0, aj1, aj2, aj3);
    } else {
        #pragma unroll 4
        for (int s = 0; s < 32; ++s) {
            int src = (lane + s) & 31;
            float pjx = __shfl_sync(0xFFFFFFFFu, qjx, src);
            float pjy = __shfl_sync(0xFFFFFFFFu, qjy, src);
            float pjz = __shfl_sync(0xFFFFFFFFu, qjz, src);
            float njx = __shfl_sync(0xFFFFFFFFu, mjx, src);
            float njy = __shfl_sync(0xFFFFFFFFu, mjy, src);
            float njz = __shfl_sync(0xFFFFFFFFu, mjz, src);
            float njs = __shfl_sync(0xFFFFFFFFu, mjs, src);

            float dn, a1, a2, a3;
            ppf_pair(pix, piy, piz, nix, niy, niz, nis,
                     pjx, pjy, pjz, njx, njy, njz, njs, dn, a1, a2, a3);

            ai0 += dn; ai1 += a1; ai2 += a2; ai3 += a3;
        }
        part[ri * NTILES + A] = make_float4(ai0, ai1, ai2, ai3);
    }
}

// ---------------------------------------------------------------------------
// Kernel D: reduce 64 partials per row (fixed order) + 4->256 linear layer
// ---------------------------------------------------------------------------
__global__ void __launch_bounds__(256)
finalize_kernel(const float4* __restrict__ part,
                const float* __restrict__ W, const float* __restrict__ b,
                float* __restrict__ out) {
    __shared__ float4 sf[NTILES];
    __shared__ float feat[4];
    int i = blockIdx.x, t = threadIdx.x;
    if (t < NTILES) sf[t] = part[i * NTILES + t];
    __syncthreads();
    if (t == 0) {
        float s0 = 0.f, s1 = 0.f, s2 = 0.f, s3 = 0.f;
        #pragma unroll
        for (int q = 0; q < NTILES; ++q) {
            float4 v = sf[q];
            s0 += v.x; s1 += v.y; s2 += v.z; s3 += v.w;
        }
        feat[0] = s0 / 2048.f; feat[1] = s1 / 2048.f;
        feat[2] = s2 / 2048.f; feat[3] = s3 / 2048.f;
    }
    __syncthreads();
    float f0 = feat[0], f1 = feat[1], f2 = feat[2], f3 = feat[3];
    float acc = f0 * W[t * 4 + 0];
    acc = acc + f1 * W[t * 4 + 1];
    acc = acc + f2 * W[t * 4 + 2];
    acc = acc + f3 * W[t * 4 + 3];
    acc = acc + b[t];
    out[i * OUTF + t] = acc;
}

extern "C" void kernel_launch(void* const* d_in, const int* in_sizes, int n_in,
                              void* d_out, int out_size) {
    const float* points = (const float*)d_in[0];   // (1, 2048, 3)
    const float* W      = (const float*)d_in[1];   // (256, 4)
    const float* b      = (const float*)d_in[2];   // (256,)
    float* out          = (float*)d_out;           // (1, 2048, 256)
    (void)in_sizes; (void)n_in; (void)out_size;

    float* soa; float* cov; float4* part;
    cudaGetSymbolAddress((void**)&soa, g_soa);
    cudaGetSymbolAddress((void**)&cov, g_cov);
    cudaGetSymbolAddress((void**)&part, g_part);

    knn_cov_kernel<<<NPTS / 4, 256>>>(points, cov);
    eigen_kernel<<<NPTS / 8, 256>>>(points, cov, soa);
    sym_ppf_kernel<<<(NTPAIRS + 3) / 4, 128>>>(soa, part);
    finalize_kernel<<<NPTS, 256>>>(part, W, b, out);
}

// round 13
// speedup vs baseline: 1.1517x; 1.0454x over previous
#include <cuda_runtime.h>
#include <cuda_bf16.h>
#include <math.h>
#include <float.h>

#define NPTS 2048
#define KNN  10
#define OUTF 256
#define NTILES 64                 // 2048 / 32
#define NTPAIRS 2080              // 64*65/2  (= 520 blocks * 4 pairs exactly)

// _rn intrinsics: immune to compiler fast-math; used on all eigen/kNN-critical math
#define FMUL(a,b)  __fmul_rn((a),(b))
#define FADD(a,b)  __fadd_rn((a),(b))
#define FSUB(a,b)  __fsub_rn((a),(b))
#define FDIV(a,b)  __fdiv_rn((a),(b))
#define FSQRT(a)   __fsqrt_rn((a))

// SoA: [0..N)=px [N..2N)=py [2N..3N)=pz [3N..4N)=nx [4N..5N)=ny [5N..6N)=nz [6N..7N)=|n|^2
__device__ float  g_soa[NPTS * 7];
// per-(row, col-tile) partial PPF sums; single writer per slot (deterministic)
__device__ float4 g_part[NPTS * NTILES];

// ---------------------------------------------------------------------------
// LAPACK fp32 building blocks (netlib-faithful, LAPACK >= 3.10 conventions)
// ---------------------------------------------------------------------------

__device__ __forceinline__ float f_sign(float a, float b) {
    return (b >= 0.f) ? fabsf(a) : -fabsf(a);
}

__device__ __forceinline__ float slapy2f(float x, float y) {
    float xa = fabsf(x), ya = fabsf(y);
    float w = fmaxf(xa, ya), z = fminf(xa, ya);
    if (z == 0.f) return w;
    float t = FDIV(z, w);
    return FMUL(w, FSQRT(FADD(1.f, FMUL(t, t))));
}

__device__ __forceinline__ void slartgf(float f, float g, float* c, float* s, float* r) {
    if (g == 0.f)      { *c = 1.f; *s = 0.f; *r = f; }
    else if (f == 0.f) { *c = 0.f; *s = (g >= 0.f) ? 1.f : -1.f; *r = fabsf(g); }
    else {
        float d  = FSQRT(FADD(FMUL(f, f), FMUL(g, g)));
        float rr = (f >= 0.f) ? d : -d;
        *c = FDIV(fabsf(f), d);
        *s = FDIV(g, rr);
        *r = rr;
    }
}

__device__ void slaev2f(float a, float b, float c,
                        float* rt1, float* rt2, float* cs1, float* sn1) {
    float sm  = FADD(a, c);
    float df  = FSUB(a, c);
    float adf = fabsf(df);
    float tb  = FADD(b, b);
    float ab  = fabsf(tb);
    float acmx, acmn;
    if (fabsf(a) > fabsf(c)) { acmx = a; acmn = c; } else { acmx = c; acmn = a; }
    float rt;
    if (adf > ab) {
        float t = FDIV(ab, adf);
        rt = FMUL(adf, FSQRT(FADD(1.f, FMUL(t, t))));
    } else if (adf < ab) {
        float t = FDIV(adf, ab);
        rt = FMUL(ab, FSQRT(FADD(1.f, FMUL(t, t))));
    } else {
        rt = FMUL(ab, FSQRT(2.f));
    }
    int sgn1;
    if (sm < 0.f) {
        *rt1 = FMUL(0.5f, FSUB(sm, rt)); sgn1 = -1;
        *rt2 = FSUB(FMUL(FDIV(acmx, *rt1), acmn), FMUL(FDIV(b, *rt1), b));
    } else if (sm > 0.f) {
        *rt1 = FMUL(0.5f, FADD(sm, rt)); sgn1 = 1;
        *rt2 = FSUB(FMUL(FDIV(acmx, *rt1), acmn), FMUL(FDIV(b, *rt1), b));
    } else {
        *rt1 = FMUL(0.5f, rt); *rt2 = FMUL(-0.5f, rt); sgn1 = 1;
    }
    float cs; int sgn2;
    if (df >= 0.f) { cs = FADD(df, rt); sgn2 =  1; }
    else           { cs = FSUB(df, rt); sgn2 = -1; }
    float acs = fabsf(cs);
    if (acs > ab) {
        float ct = FDIV(-tb, cs);
        *sn1 = FDIV(1.f, FSQRT(FADD(1.f, FMUL(ct, ct))));
        *cs1 = FMUL(ct, *sn1);
    } else {
        if (ab == 0.f) { *cs1 = 1.f; *sn1 = 0.f; }
        else {
            float tn = FDIV(-cs, tb);
            *cs1 = FDIV(1.f, FSQRT(FADD(1.f, FMUL(tn, tn))));
            *sn1 = FMUL(tn, *cs1);
        }
    }
    if (sgn1 == sgn2) { float tn = *cs1; *cs1 = -(*sn1); *sn1 = tn; }
}

// ssteqr('I', n=3), register-resident; control flow/arithmetic == netlib
__device__ void ssteqr3_reg(float& d0, float& d1, float& d2,
                            float& e0, float& e1,
                            float& za0, float& za1, float& za2,
                            float& zb0, float& zb1, float& zb2,
                            float& zc0, float& zc1, float& zc2) {
    const float eps    = 5.9604645e-8f;
    const float eps2   = eps * eps;
    const float safmin = 1.17549435e-38f;
    float wc0 = 0.f, wc1 = 0.f, ws0 = 0.f, ws1 = 0.f;

    auto dget = [&](int i) -> float { return i == 0 ? d0 : (i == 1 ? d1 : d2); };
    auto dset = [&](int i, float v) { if (i == 0) d0 = v; else if (i == 1) d1 = v; else d2 = v; };
    auto eget = [&](int i) -> float { return i == 0 ? e0 : e1; };
    auto eset = [&](int i, float v) { if (i == 0) e0 = v; else e1 = v; };
    auto wcget = [&](int i) -> float { return i == 0 ? wc0 : wc1; };
    auto wcset = [&](int i, float v) { if (i == 0) wc0 = v; else wc1 = v; };
    auto wsget = [&](int i) -> float { return i == 0 ? ws0 : ws1; };
    auto wsset = [&](int i, float v) { if (i == 0) ws0 = v; else ws1 = v; };

    auto rot = [&](int cb1, float c, float s) {
        if (cb1 == 1) {
            float t;
            t = zb0; zb0 = FSUB(FMUL(c, t), FMUL(s, za0)); za0 = FADD(FMUL(s, t), FMUL(c, za0));
            t = zb1; zb1 = FSUB(FMUL(c, t), FMUL(s, za1)); za1 = FADD(FMUL(s, t), FMUL(c, za1));
            t = zb2; zb2 = FSUB(FMUL(c, t), FMUL(s, za2)); za2 = FADD(FMUL(s, t), FMUL(c, za2));
        } else {
            float t;
            t = zc0; zc0 = FSUB(FMUL(c, t), FMUL(s, zb0)); zb0 = FADD(FMUL(s, t), FMUL(c, zb0));
            t = zc1; zc1 = FSUB(FMUL(c, t), FMUL(s, zb1)); zb1 = FADD(FMUL(s, t), FMUL(c, zb1));
            t = zc2; zc2 = FSUB(FMUL(c, t), FMUL(s, zb2)); zb2 = FADD(FMUL(s, t), FMUL(c, zb2));
        }
    };
    auto slasr_bL = [&](int lcol, int mm) {
        for (int j = mm - 1; j >= 1; --j) {
            float c = wcget(lcol - 2 + j), s = wsget(lcol - 2 + j);
            if (c != 1.f || s != 0.f) rot(lcol + j - 1, c, s);
        }
    };
    auto slasr_fL = [&](int lcol, int mm) {
        for (int j = 1; j <= mm - 1; ++j) {
            float c = wcget(lcol - 2 + j), s = wsget(lcol - 2 + j);
            if (c != 1.f || s != 0.f) rot(lcol + j - 1, c, s);
        }
    };

    int l1, l, lsv, lend, lendsv, m, i, jtot, nmaxit;
    float p, g, r, s, c, f, bb, rt1, rt2, anorm, tst;
    nmaxit = 90; jtot = 0; l1 = 1;

L10:
    if (l1 > 3) goto L160;
    if (l1 > 1) eset(l1 - 2, 0.f);
    if (l1 <= 2) {
        for (m = l1; m <= 2; ++m) {
            tst = fabsf(eget(m - 1));
            if (tst == 0.f) goto L30;
            if (tst <= FMUL(FMUL(FSQRT(fabsf(dget(m - 1))), FSQRT(fabsf(dget(m)))), eps)) {
                eset(m - 1, 0.f); goto L30;
            }
        }
    }
    m = 3;
L30:
    l = l1; lsv = l; lend = m; lendsv = lend; l1 = m + 1;
    if (lend == l) goto L10;
    anorm = 0.f;
    for (i = l; i <= lend; ++i)     anorm = fmaxf(anorm, fabsf(dget(i - 1)));
    for (i = l; i <= lend - 1; ++i) anorm = fmaxf(anorm, fabsf(eget(i - 1)));
    if (anorm == 0.f) goto L10;
    if (fabsf(dget(lend - 1)) < fabsf(dget(l - 1))) { lend = lsv; l = lendsv; }
    if (lend > l) goto L40; else goto L90;

L40: // QL
    if (l != lend) {
        for (m = l; m <= lend - 1; ++m) {
            tst = FMUL(eget(m - 1), eget(m - 1));
            if (tst <= FADD(FMUL(FMUL(eps2, fabsf(dget(m - 1))), fabsf(dget(m))), safmin)) goto L60;
        }
    }
    m = lend;
L60:
    if (m < lend) eset(m - 1, 0.f);
    p = dget(l - 1);
    if (m == l) goto L80;
    if (m == l + 1) {
        slaev2f(dget(l - 1), eget(l - 1), dget(l), &rt1, &rt2, &c, &s);
        wcset(l - 1, c); wsset(l - 1, s);
        slasr_bL(l, 2);
        dset(l - 1, rt1); dset(l, rt2); eset(l - 1, 0.f);
        l += 2;
        if (l <= lend) goto L40;
        goto L140;
    }
    if (jtot == nmaxit) goto L140;
    jtot++;
    g = FDIV(FSUB(dget(l), p), FMUL(2.f, eget(l - 1)));
    r = slapy2f(g, 1.f);
    g = FADD(FSUB(dget(m - 1), p), FDIV(eget(l - 1), FADD(g, f_sign(r, g))));
    s = 1.f; c = 1.f; p = 0.f;
    for (i = m - 1; i >= l; --i) {
        f  = FMUL(s, eget(i - 1));
        bb = FMUL(c, eget(i - 1));
        slartgf(g, f, &c, &s, &r);
        if (i != m - 1) eset(i, r);
        g = FSUB(dget(i), p);
        r = FADD(FMUL(FSUB(dget(i - 1), g), s), FMUL(FMUL(2.f, c), bb));
        p = FMUL(s, r);
        dset(i, FADD(g, p));
        g = FSUB(FMUL(c, r), bb);
        wcset(i - 1, c); wsset(i - 1, -s);
    }
    slasr_bL(l, m - l + 1);
    dset(l - 1, FSUB(dget(l - 1), p));
    eset(l - 1, g);
    goto L40;
L80:
    dset(l - 1, p);
    l++;
    if (l <= lend) goto L40;
    goto L140;

L90: // QR
    if (l != lend) {
        for (m = l; m >= lend + 1; --m) {
            tst = FMUL(eget(m - 2), eget(m - 2));
            if (tst <= FADD(FMUL(FMUL(eps2, fabsf(dget(m - 1))), fabsf(dget(m - 2))), safmin)) goto L110;
        }
    }
    m = lend;
L110:
    if (m > lend) eset(m - 2, 0.f);
    p = dget(l - 1);
    if (m == l) goto L130;
    if (m == l - 1) {
        slaev2f(dget(l - 2), eget(l - 2), dget(l - 1), &rt1, &rt2, &c, &s);
        wcset(m - 1, c); wsset(m - 1, s);
        slasr_fL(l - 1, 2);
        dset(l - 2, rt1); dset(l - 1, rt2); eset(l - 2, 0.f);
        l -= 2;
        if (l >= lend) goto L90;
        goto L140;
    }
    if (jtot == nmaxit) goto L140;
    jtot++;
    g = FDIV(FSUB(dget(l - 2), p), FMUL(2.f, eget(l - 2)));
    r = slapy2f(g, 1.f);
    g = FADD(FSUB(dget(m - 1), p), FDIV(eget(l - 2), FADD(g, f_sign(r, g))));
    s = 1.f; c = 1.f; p = 0.f;
    for (i = m; i <= l - 1; ++i) {
        f  = FMUL(s, eget(i - 1));
        bb = FMUL(c, eget(i - 1));
        slartgf(g, f, &c, &s, &r);
        if (i != m) eset(i - 2, r);
        g = FSUB(dget(i - 1), p);
        r = FADD(FMUL(FSUB(dget(i), g), s), FMUL(FMUL(2.f, c), bb));
        p = FMUL(s, r);
        dset(i - 1, FADD(g, p));
        g = FSUB(FMUL(c, r), bb);
        wcset(i - 1, c); wsset(i - 1, s);
    }
    slasr_fL(m, l - m + 1);
    dset(l - 1, FSUB(dget(l - 1), p));
    eset(l - 2, g);
    goto L90;
L130:
    dset(l - 1, p);
    l--;
    if (l >= lend) goto L90;
    goto L140;

L140:
    if (jtot < nmaxit) goto L10;
    goto L160;

L160:
    {
        auto swapcol = [&](int c1, int c2) {
            float t;
            if (c1 == 0 && c2 == 1) {
                t = za0; za0 = zb0; zb0 = t;
                t = za1; za1 = zb1; zb1 = t;
                t = za2; za2 = zb2; zb2 = t;
            } else if (c1 == 0) {
                t = za0; za0 = zc0; zc0 = t;
                t = za1; za1 = zc1; zc1 = t;
                t = za2; za2 = zc2; zc2 = t;
            } else {
                t = zb0; zb0 = zc0; zc0 = t;
                t = zb1; zb1 = zc1; zc1 = t;
                t = zb2; zb2 = zc2; zc2 = t;
            }
        };
        for (int ii = 2; ii <= 3; ++ii) {
            int ia = ii - 1, k = ia;
            float pp = dget(ia - 1);
            for (int j = ii; j <= 3; ++j)
                if (dget(j - 1) < pp) { k = j; pp = dget(j - 1); }
            if (k != ia) {
                dset(k - 1, dget(ia - 1)); dset(ia - 1, pp);
                swapcol(ia - 1, k - 1);
            }
        }
    }
}

__device__ void smallest_eigvec3(float a11, float a21, float a31,
                                 float a22, float a32, float a33,
                                 float* nrm) {
    float alpha = a21;
    float xnorm = fabsf(a31);
    float tau1, v3, eh;
    if (xnorm == 0.f) {
        tau1 = 0.f; eh = alpha; v3 = 0.f;
    } else {
        float beta = -f_sign(slapy2f(alpha, xnorm), alpha);
        tau1 = FDIV(FSUB(beta, alpha), beta);
        v3   = FMUL(a31, FDIV(1.f, FSUB(alpha, beta)));
        eh   = beta;
    }
    if (tau1 != 0.f) {
        float x1 = FMUL(tau1, FADD(a22, FMUL(a32, v3)));
        float x2 = FMUL(tau1, FADD(a32, FMUL(a33, v3)));
        float al = FMUL(FMUL(-0.5f, tau1), FADD(x1, FMUL(x2, v3)));
        float w1 = FADD(x1, al);
        float w2 = FADD(x2, FMUL(al, v3));
        a22 = FSUB(a22, FMUL(2.f, w1));
        a32 = FSUB(a32, FADD(FMUL(v3, w1), w2));
        a33 = FSUB(a33, FMUL(2.f, FMUL(v3, w2)));
    }
    float d0 = a11, d1 = a22, d2 = a33;
    float e0 = eh, e1 = a32;
    float za0 = 1.f, za1 = 0.f, za2 = 0.f;
    float zb0 = 0.f, zb1 = 1.f, zb2 = 0.f;
    float zc0 = 0.f, zc1 = 0.f, zc2 = 1.f;

    ssteqr3_reg(d0, d1, d2, e0, e1,
                za0, za1, za2, zb0, zb1, zb2, zc0, zc1, zc2);

    float z0 = za0, z1 = za1, z2 = za2;
    if (tau1 != 0.f) {
        float t = FMUL(tau1, FADD(z1, FMUL(v3, z2)));
        z1 = FSUB(z1, t);
        z2 = FSUB(z2, FMUL(t, v3));
    }
    nrm[0] = z0; nrm[1] = z1; nrm[2] = z2;
}

// ---------------------------------------------------------------------------
// Kernel A: kNN (2 warps/point, u64 keys == top_k's stable (sq, idx) order)
// + covariance + eigensolver computed WARP-UNIFORMLY (all 32 lanes redundant,
// zero divergence); lane 0 writes the SoA.
// ---------------------------------------------------------------------------
__global__ void __launch_bounds__(256)
knn_normals_kernel(const float* __restrict__ pts, float* __restrict__ soa) {
    __shared__ float sx[NPTS], sy[NPTS], sz[NPTS];
    __shared__ unsigned long long scand[4][2][11];
    int tid = threadIdx.x;
    for (int j = tid; j < NPTS; j += 256) {
        sx[j] = pts[j * 3 + 0];
        sy[j] = pts[j * 3 + 1];
        sz[j] = pts[j * 3 + 2];
    }
    __syncthreads();

    int warp = tid >> 5, lane = tid & 31;
    int wp   = warp >> 1;
    int half = warp & 1;
    int p    = blockIdx.x * 4 + wp;

    float pix = sx[p], piy = sy[p], piz = sz[p];

    unsigned long long kv[KNN + 1];
    #pragma unroll
    for (int q = 0; q <= KNN; ++q) kv[q] = 0xFFFFFFFFFFFFFFFFull;

    int base = half * (NPTS / 2);
    #pragma unroll 4
    for (int s = 0; s < NPTS / 64; ++s) {
        int j = base + s * 32 + lane;
        float dx = FSUB(pix, sx[j]);
        float dy = FSUB(piy, sy[j]);
        float dz = FSUB(piz, sz[j]);
        float sq = FADD(FADD(FMUL(dx, dx), FMUL(dy, dy)), FMUL(dz, dz));
        unsigned long long key =
            ((unsigned long long)__float_as_uint(sq) << 32) | (unsigned)j;
        if (key < kv[KNN]) {
            kv[KNN] = key;
            #pragma unroll
            for (int q = KNN; q > 0; --q) {
                unsigned long long a = kv[q - 1], b = kv[q];
                kv[q - 1] = (a < b) ? a : b;
                kv[q]     = (a < b) ? b : a;
            }
        }
    }

    // intra-warp merge: 11 rounds of warp-min over per-lane sorted heads
    #pragma unroll
    for (int r = 0; r <= KNN; ++r) {
        unsigned long long mykey = kv[0];
        unsigned long long m = mykey;
        #pragma unroll
        for (int off = 16; off > 0; off >>= 1) {
            unsigned long long o = __shfl_xor_sync(0xFFFFFFFFu, m, off);
            m = (o < m) ? o : m;
        }
        if (lane == r) scand[wp][half][r] = m;
        if (mykey == m) {
            #pragma unroll
            for (int q = 0; q < KNN; ++q) kv[q] = kv[q + 1];
            kv[KNN] = 0xFFFFFFFFFFFFFFFFull;
        }
    }
    __syncthreads();

    if (half == 0) {
        // cross-merge the two sorted 11-lists (22 unique keys)
        unsigned long long key = 0xFFFFFFFFFFFFFFFFull;
        if (lane < 11)       key = scand[wp][0][lane];
        else if (lane < 22)  key = scand[wp][1][lane - 11];

        int nbr[KNN + 1];
        #pragma unroll
        for (int r = 0; r <= KNN; ++r) {
            unsigned long long m = key;
            #pragma unroll
            for (int off = 16; off > 0; off >>= 1) {
                unsigned long long o = __shfl_xor_sync(0xFFFFFFFFu, m, off);
                m = (o < m) ? o : m;
            }
            nbr[r] = (int)(unsigned)(m & 0xFFFFFFFFull);
            if (key == m) key = 0xFFFFFFFFFFFFFFFFull;
        }

        // covariance + eigensolver: WARP-UNIFORM (all lanes identical work,
        // smem broadcast reads, zero divergence). Lane 0 writes.
        float nx[KNN], ny[KNN], nz[KNN];
        float mx = 0.f, my = 0.f, mz = 0.f;
        #pragma unroll
        for (int k = 0; k < KNN; ++k) {
            int j = nbr[k + 1];
            nx[k] = sx[j]; ny[k] = sy[j]; nz[k] = sz[j];
            mx = FADD(mx, nx[k]); my = FADD(my, ny[k]); mz = FADD(mz, nz[k]);
        }
        mx = FDIV(mx, 10.f); my = FDIV(my, 10.f); mz = FDIV(mz, 10.f);

        float c00 = 0.f, c10 = 0.f, c20 = 0.f, c11 = 0.f, c21 = 0.f, c22 = 0.f;
        #pragma unroll
        for (int k = 0; k < KNN; ++k) {
            float cx = FSUB(nx[k], mx);
            float cy = FSUB(ny[k], my);
            float cz = FSUB(nz[k], mz);
            c00 = FADD(c00, FMUL(cx, cx));
            c10 = FADD(c10, FMUL(cy, cx));
            c20 = FADD(c20, FMUL(cz, cx));
            c11 = FADD(c11, FMUL(cy, cy));
            c21 = FADD(c21, FMUL(cz, cy));
            c22 = FADD(c22, FMUL(cz, cz));
        }
        c00 = FDIV(c00, 10.f); c10 = FDIV(c10, 10.f); c20 = FDIV(c20, 10.f);
        c11 = FDIV(c11, 10.f); c21 = FDIV(c21, 10.f); c22 = FDIV(c22, 10.f);

        float nrm[3];
        smallest_eigvec3(c00, c10, c20, c11, c21, c22, nrm);

        if (lane == 0) {
            soa[p]            = pix;
            soa[NPTS + p]     = piy;
            soa[2 * NPTS + p] = piz;
            soa[3 * NPTS + p] = nrm[0];
            soa[4 * NPTS + p] = nrm[1];
            soa[5 * NPTS + p] = nrm[2];
            soa[6 * NPTS + p] = nrm[0] * nrm[0] + nrm[1] * nrm[1] + nrm[2] * nrm[2];
        }
    }
}

// ---------------------------------------------------------------------------
// Fast atan2 for y >= 0 (result in [0, pi]); cephes coefficients, ~1e-7 abs err
// ---------------------------------------------------------------------------
__device__ __forceinline__ float fast_atan2_pos(float y, float x) {
    const float PI    = 3.14159265358979323846f;
    const float PIO2  = 1.57079632679489661923f;
    const float PIO4  = 0.78539816339744830962f;
    const float TAN8  = 0.41421356237309504880f;

    float ax = fabsf(x);
    float mn = fminf(y, ax), mx = fmaxf(y, ax);
    float t = (mx == 0.f) ? 0.f : __fdividef(mn, mx);

    float add = 0.f;
    if (t > TAN8) { t = __fdividef(t - 1.f, t + 1.f); add = PIO4; }

    float z = t * t;
    float p = 8.05374449538e-2f;
    p = p * z - 1.38776856032e-1f;
    p = p * z + 1.99777106478e-1f;
    p = p * z - 3.33329491539e-1f;
    float r = fmaf(p * z, t, t) + add;

    if (y > ax)  r = PIO2 - r;
    if (x < 0.f) r = PI - r;
    return r;
}

__device__ __forceinline__ void ppf_pair(
    float pix, float piy, float piz, float nix, float niy, float niz, float nis,
    float pjx, float pjy, float pjz, float njx, float njy, float njz, float njs,
    float& dn, float& a1, float& a2, float& a3)
{
    float dx = pix - pjx, dy = piy - pjy, dz = piz - pjz;
    float sq = dx * dx + dy * dy + dz * dz;
    dn = (sq > 0.f) ? sq * rsqrtf(sq) : 0.f;

    float dot1 = nix * dx + niy * dy + niz * dz;
    float csq1 = fmaf(nis, sq, -(dot1 * dot1));
    float cn1  = (csq1 > 0.f) ? csq1 * rsqrtf(csq1) : 0.f;
    a1 = fast_atan2_pos(cn1, dot1);

    float dot2 = njx * dx + njy * dy + njz * dz;
    float csq2 = fmaf(njs, sq, -(dot2 * dot2));
    float cn2  = (csq2 > 0.f) ? csq2 * rsqrtf(csq2) : 0.f;
    a2 = fast_atan2_pos(cn2, dot2);

    float dot3 = nix * njx + niy * njy + niz * njz;
    float csq3 = fmaf(nis, njs, -(dot3 * dot3));
    float cn3  = (csq3 > 0.f) ? csq3 * rsqrtf(csq3) : 0.f;
    a3 = fast_atan2_pos(cn3, dot3);
}

// ---------------------------------------------------------------------------
// Kernel B: symmetric PPF. TWO warps per unordered 32x32 tile pair, in the
// SAME block: warp-half sh handles steps [16*sh, 16*sh+16). Half 1 posts its
// partials to smem; half 0 adds (fixed order) and does the single write.
// F(j,i) = [dn, pi - a2(i,j), pi - a1(i,j), a3] (exact identities).
// NTPAIRS = 520 * 4 exactly, so every warp has a valid pair (no early exits).
// ---------------------------------------------------------------------------
__global__ void __launch_bounds__(256)
sym_ppf_kernel(const float* __restrict__ soa, float4* __restrict__ part) {
    const float PI = 3.14159265358979323846f;
    __shared__ float sbuf[4][32][9];   // [pair][lane][8 partials], pad 9 vs banks

    int wid  = threadIdx.x >> 5;       // 0..7
    int ps   = wid >> 1;               // pair slot 0..3
    int sh   = wid & 1;                // step half
    int lane = threadIdx.x & 31;
    int wt   = blockIdx.x * 4 + ps;    // < NTPAIRS always

    int A = (int)((sqrtf(8.f * (float)wt + 1.f) - 1.f) * 0.5f);
    while ((A + 1) * (A + 2) / 2 <= wt) ++A;
    while (A * (A + 1) / 2 > wt) --A;
    int B = wt - A * (A + 1) / 2;

    const float* px = soa;
    const float* py = soa + NPTS;
    const float* pz = soa + 2 * NPTS;
    const float* nx = soa + 3 * NPTS;
    const float* ny = soa + 4 * NPTS;
    const float* nz = soa + 5 * NPTS;
    const float* ns = soa + 6 * NPTS;

    int ri = B * 32 + lane;
    int rj = A * 32 + lane;
    float pix = __ldg(&px[ri]), piy = __ldg(&py[ri]), piz = __ldg(&pz[ri]);
    float nix = __ldg(&nx[ri]), niy = __ldg(&ny[ri]), niz = __ldg(&nz[ri]);
    float nis = __ldg(&ns[ri]);
    float qjx = __ldg(&px[rj]), qjy = __ldg(&py[rj]), qjz = __ldg(&pz[rj]);
    float mjx = __ldg(&nx[rj]), mjy = __ldg(&ny[rj]), mjz = __ldg(&nz[rj]);
    float mjs = __ldg(&ns[rj]);

    float ai0 = 0.f, ai1 = 0.f, ai2 = 0.f, ai3 = 0.f;
    float aj0 = 0.f, aj1 = 0.f, aj2 = 0.f, aj3 = 0.f;
    int s0i = sh * 16;

    if (A != B) {
        #pragma unroll 4
        for (int s = s0i; s < s0i + 16; ++s) {
            int src = (lane + s) & 31;
            float pjx = __shfl_sync(0xFFFFFFFFu, qjx, src);
            float pjy = __shfl_sync(0xFFFFFFFFu, qjy, src);
            float pjz = __shfl_sync(0xFFFFFFFFu, qjz, src);
            float njx = __shfl_sync(0xFFFFFFFFu, mjx, src);
            float njy = __shfl_sync(0xFFFFFFFFu, mjy, src);
            float njz = __shfl_sync(0xFFFFFFFFu, mjz, src);
            float njs = __shfl_sync(0xFFFFFFFFu, mjs, src);

            float dn, a1, a2, a3;
            ppf_pair(pix, piy, piz, nix, niy, niz, nis,
                     pjx, pjy, pjz, njx, njy, njz, njs, dn, a1, a2, a3);

            ai0 += dn; ai1 += a1; ai2 += a2; ai3 += a3;

            float c0 = dn, c1 = PI - a2, c2 = PI - a1, c3 = a3;
            int rsrc = (lane - s) & 31;
            aj0 += __shfl_sync(0xFFFFFFFFu, c0, rsrc);
            aj1 += __shfl_sync(0xFFFFFFFFu, c1, rsrc);
            aj2 += __shfl_sync(0xFFFFFFFFu, c2, rsrc);
            aj3 += __shfl_sync(0xFFFFFFFFu, c3, rsrc);
        }
    } else {
        #pragma unroll 4
        for (int s = s0i; s < s0i + 16; ++s) {
            int src = (lane + s) & 31;
            float pjx = __shfl_sync(0xFFFFFFFFu, qjx, src);
            float pjy = __shfl_sync(0xFFFFFFFFu, qjy, src);
            float pjz = __shfl_sync(0xFFFFFFFFu, qjz, src);
            float njx = __shfl_sync(0xFFFFFFFFu, mjx, src);
            float njy = __shfl_sync(0xFFFFFFFFu, mjy, src);
            float njz = __shfl_sync(0xFFFFFFFFu, mjz, src);
            float njs = __shfl_sync(0xFFFFFFFFu, mjs, src);

            float dn, a1, a2, a3;
            ppf_pair(pix, piy, piz, nix, niy, niz, nis,
                     pjx, pjy, pjz, njx, njy, njz, njs, dn, a1, a2, a3);

            ai0 += dn; ai1 += a1; ai2 += a2; ai3 += a3;
        }
    }

    if (sh == 1) {
        sbuf[ps][lane][0] = ai0; sbuf[ps][lane][1] = ai1;
        sbuf[ps][lane][2] = ai2; sbuf[ps][lane][3] = ai3;
        sbuf[ps][lane][4] = aj0; sbuf[ps][lane][5] = aj1;
        sbuf[ps][lane][6] = aj2; sbuf[ps][lane][7] = aj3;
    }
    __syncthreads();
    if (sh == 0) {
        ai0 += sbuf[ps][lane][0]; ai1 += sbuf[ps][lane][1];
        ai2 += sbuf[ps][lane][2]; ai3 += sbuf[ps][lane][3];
        aj0 += sbuf[ps][lane][4]; aj1 += sbuf[ps][lane][5];
        aj2 += sbuf[ps][lane][6]; aj3 += sbuf[ps][lane][7];

        part[ri * NTILES + A] = make_float4(ai0, ai1, ai2, ai3);
        if (A != B)
            part[rj * NTILES + B] = make_float4(aj0, aj1, aj2, aj3);
    }
}

// ---------------------------------------------------------------------------
// Kernel C: tree-reduce 64 partials per row + 4->256 linear layer
// ---------------------------------------------------------------------------
__global__ void __launch_bounds__(256)
finalize_kernel(const float4* __restrict__ part,
                const float* __restrict__ W, const float* __restrict__ b,
                float* __restrict__ out) {
    __shared__ float4 wsum[2];
    __shared__ float feat[4];
    int i = blockIdx.x, t = threadIdx.x;

    if (t < 64) {
        float4 v = part[i * NTILES + t];
        #pragma unroll
        for (int off = 16; off > 0; off >>= 1) {
            v.x += __shfl_down_sync(0xFFFFFFFFu, v.x, off);
            v.y += __shfl_down_sync(0xFFFFFFFFu, v.y, off);
            v.z += __shfl_down_sync(0xFFFFFFFFu, v.z, off);
            v.w += __shfl_down_sync(0xFFFFFFFFu, v.w, off);
        }
        if ((t & 31) == 0) wsum[t >> 5] = v;
    }
    __syncthreads();
    if (t == 0) {
        float4 a = wsum[0], c = wsum[1];
        feat[0] = (a.x + c.x) / 2048.f;
        feat[1] = (a.y + c.y) / 2048.f;
        feat[2] = (a.z + c.z) / 2048.f;
        feat[3] = (a.w + c.w) / 2048.f;
    }
    __syncthreads();
    float f0 = feat[0], f1 = feat[1], f2 = feat[2], f3 = feat[3];
    float acc = f0 * W[t * 4 + 0];
    acc = acc + f1 * W[t * 4 + 1];
    acc = acc + f2 * W[t * 4 + 2];
    acc = acc + f3 * W[t * 4 + 3];
    acc = acc + b[t];
    out[i * OUTF + t] = acc;
}

extern "C" void kernel_launch(void* const* d_in, const int* in_sizes, int n_in,
                              void* d_out, int out_size) {
    const float* points = (const float*)d_in[0];   // (1, 2048, 3)
    const float* W      = (const float*)d_in[1];   // (256, 4)
    const float* b      = (const float*)d_in[2];   // (256,)
    float* out          = (float*)d_out;           // (1, 2048, 256)
    (void)in_sizes; (void)n_in; (void)out_size;

    float* soa; float4* part;
    cudaGetSymbolAddress((void**)&soa, g_soa);
    cudaGetSymbolAddress((void**)&part, g_part);

    knn_normals_kernel<<<NPTS / 4, 256>>>(points, soa);
    sym_ppf_kernel<<<NTPAIRS / 4, 256>>>(soa, part);
    finalize_kernel<<<NPTS, 256>>>(part, W, b, out);
}

// round 14
// speedup vs baseline: 1.5282x; 1.3269x over previous
#include <cuda_runtime.h>
#include <cuda_bf16.h>
#include <math.h>
#include <float.h>

#define NPTS 2048
#define KNN  10
#define OUTF 256
#define NTILES 64                 // 2048 / 32
#define NTPAIRS 2080              // 64*65/2  (= 520 blocks * 4 pairs exactly)
#define FULLM 0xFFFFFFFFu

// _rn intrinsics: immune to compiler fast-math; used on all eigen/kNN-critical math
#define FMUL(a,b)  __fmul_rn((a),(b))
#define FADD(a,b)  __fadd_rn((a),(b))
#define FSUB(a,b)  __fsub_rn((a),(b))
#define FDIV(a,b)  __fdiv_rn((a),(b))
#define FSQRT(a)   __fsqrt_rn((a))

// SoA: [0..N)=px [N..2N)=py [2N..3N)=pz [3N..4N)=nx [4N..5N)=ny [5N..6N)=nz [6N..7N)=|n|^2
__device__ float  g_soa[NPTS * 7];
// per-(row, col-tile) partial PPF sums; single writer per slot (deterministic)
__device__ float4 g_part[NPTS * NTILES];

// ---------------------------------------------------------------------------
// LAPACK fp32 building blocks (netlib-faithful, LAPACK >= 3.10 conventions)
// ---------------------------------------------------------------------------

__device__ __forceinline__ float f_sign(float a, float b) {
    return (b >= 0.f) ? fabsf(a) : -fabsf(a);
}

__device__ __forceinline__ float slapy2f(float x, float y) {
    float xa = fabsf(x), ya = fabsf(y);
    float w = fmaxf(xa, ya), z = fminf(xa, ya);
    if (z == 0.f) return w;
    float t = FDIV(z, w);
    return FMUL(w, FSQRT(FADD(1.f, FMUL(t, t))));
}

__device__ __forceinline__ void slartgf(float f, float g, float* c, float* s, float* r) {
    if (g == 0.f)      { *c = 1.f; *s = 0.f; *r = f; }
    else if (f == 0.f) { *c = 0.f; *s = (g >= 0.f) ? 1.f : -1.f; *r = fabsf(g); }
    else {
        float d  = FSQRT(FADD(FMUL(f, f), FMUL(g, g)));
        float rr = (f >= 0.f) ? d : -d;
        *c = FDIV(fabsf(f), d);
        *s = FDIV(g, rr);
        *r = rr;
    }
}

__device__ void slaev2f(float a, float b, float c,
                        float* rt1, float* rt2, float* cs1, float* sn1) {
    float sm  = FADD(a, c);
    float df  = FSUB(a, c);
    float adf = fabsf(df);
    float tb  = FADD(b, b);
    float ab  = fabsf(tb);
    float acmx, acmn;
    if (fabsf(a) > fabsf(c)) { acmx = a; acmn = c; } else { acmx = c; acmn = a; }
    float rt;
    if (adf > ab) {
        float t = FDIV(ab, adf);
        rt = FMUL(adf, FSQRT(FADD(1.f, FMUL(t, t))));
    } else if (adf < ab) {
        float t = FDIV(adf, ab);
        rt = FMUL(ab, FSQRT(FADD(1.f, FMUL(t, t))));
    } else {
        rt = FMUL(ab, FSQRT(2.f));
    }
    int sgn1;
    if (sm < 0.f) {
        *rt1 = FMUL(0.5f, FSUB(sm, rt)); sgn1 = -1;
        *rt2 = FSUB(FMUL(FDIV(acmx, *rt1), acmn), FMUL(FDIV(b, *rt1), b));
    } else if (sm > 0.f) {
        *rt1 = FMUL(0.5f, FADD(sm, rt)); sgn1 = 1;
        *rt2 = FSUB(FMUL(FDIV(acmx, *rt1), acmn), FMUL(FDIV(b, *rt1), b));
    } else {
        *rt1 = FMUL(0.5f, rt); *rt2 = FMUL(-0.5f, rt); sgn1 = 1;
    }
    float cs; int sgn2;
    if (df >= 0.f) { cs = FADD(df, rt); sgn2 =  1; }
    else           { cs = FSUB(df, rt); sgn2 = -1; }
    float acs = fabsf(cs);
    if (acs > ab) {
        float ct = FDIV(-tb, cs);
        *sn1 = FDIV(1.f, FSQRT(FADD(1.f, FMUL(ct, ct))));
        *cs1 = FMUL(ct, *sn1);
    } else {
        if (ab == 0.f) { *cs1 = 1.f; *sn1 = 0.f; }
        else {
            float tn = FDIV(-cs, tb);
            *cs1 = FDIV(1.f, FSQRT(FADD(1.f, FMUL(tn, tn))));
            *sn1 = FMUL(tn, *cs1);
        }
    }
    if (sgn1 == sgn2) { float tn = *cs1; *cs1 = -(*sn1); *sn1 = tn; }
}

// ssteqr('I', n=3), register-resident; control flow/arithmetic == netlib
__device__ void ssteqr3_reg(float& d0, float& d1, float& d2,
                            float& e0, float& e1,
                            float& za0, float& za1, float& za2,
                            float& zb0, float& zb1, float& zb2,
                            float& zc0, float& zc1, float& zc2) {
    const float eps    = 5.9604645e-8f;
    const float eps2   = eps * eps;
    const float safmin = 1.17549435e-38f;
    float wc0 = 0.f, wc1 = 0.f, ws0 = 0.f, ws1 = 0.f;

    auto dget = [&](int i) -> float { return i == 0 ? d0 : (i == 1 ? d1 : d2); };
    auto dset = [&](int i, float v) { if (i == 0) d0 = v; else if (i == 1) d1 = v; else d2 = v; };
    auto eget = [&](int i) -> float { return i == 0 ? e0 : e1; };
    auto eset = [&](int i, float v) { if (i == 0) e0 = v; else e1 = v; };
    auto wcget = [&](int i) -> float { return i == 0 ? wc0 : wc1; };
    auto wcset = [&](int i, float v) { if (i == 0) wc0 = v; else wc1 = v; };
    auto wsget = [&](int i) -> float { return i == 0 ? ws0 : ws1; };
    auto wsset = [&](int i, float v) { if (i == 0) ws0 = v; else ws1 = v; };

    auto rot = [&](int cb1, float c, float s) {
        if (cb1 == 1) {
            float t;
            t = zb0; zb0 = FSUB(FMUL(c, t), FMUL(s, za0)); za0 = FADD(FMUL(s, t), FMUL(c, za0));
            t = zb1; zb1 = FSUB(FMUL(c, t), FMUL(s, za1)); za1 = FADD(FMUL(s, t), FMUL(c, za1));
            t = zb2; zb2 = FSUB(FMUL(c, t), FMUL(s, za2)); za2 = FADD(FMUL(s, t), FMUL(c, za2));
        } else {
            float t;
            t = zc0; zc0 = FSUB(FMUL(c, t), FMUL(s, zb0)); zb0 = FADD(FMUL(s, t), FMUL(c, zb0));
            t = zc1; zc1 = FSUB(FMUL(c, t), FMUL(s, zb1)); zb1 = FADD(FMUL(s, t), FMUL(c, zb1));
            t = zc2; zc2 = FSUB(FMUL(c, t), FMUL(s, zb2)); zb2 = FADD(FMUL(s, t), FMUL(c, zb2));
        }
    };
    auto slasr_bL = [&](int lcol, int mm) {
        for (int j = mm - 1; j >= 1; --j) {
            float c = wcget(lcol - 2 + j), s = wsget(lcol - 2 + j);
            if (c != 1.f || s != 0.f) rot(lcol + j - 1, c, s);
        }
    };
    auto slasr_fL = [&](int lcol, int mm) {
        for (int j = 1; j <= mm - 1; ++j) {
            float c = wcget(lcol - 2 + j), s = wsget(lcol - 2 + j);
            if (c != 1.f || s != 0.f) rot(lcol + j - 1, c, s);
        }
    };

    int l1, l, lsv, lend, lendsv, m, i, jtot, nmaxit;
    float p, g, r, s, c, f, bb, rt1, rt2, anorm, tst;
    nmaxit = 90; jtot = 0; l1 = 1;

L10:
    if (l1 > 3) goto L160;
    if (l1 > 1) eset(l1 - 2, 0.f);
    if (l1 <= 2) {
        for (m = l1; m <= 2; ++m) {
            tst = fabsf(eget(m - 1));
            if (tst == 0.f) goto L30;
            if (tst <= FMUL(FMUL(FSQRT(fabsf(dget(m - 1))), FSQRT(fabsf(dget(m)))), eps)) {
                eset(m - 1, 0.f); goto L30;
            }
        }
    }
    m = 3;
L30:
    l = l1; lsv = l; lend = m; lendsv = lend; l1 = m + 1;
    if (lend == l) goto L10;
    anorm = 0.f;
    for (i = l; i <= lend; ++i)     anorm = fmaxf(anorm, fabsf(dget(i - 1)));
    for (i = l; i <= lend - 1; ++i) anorm = fmaxf(anorm, fabsf(eget(i - 1)));
    if (anorm == 0.f) goto L10;
    if (fabsf(dget(lend - 1)) < fabsf(dget(l - 1))) { lend = lsv; l = lendsv; }
    if (lend > l) goto L40; else goto L90;

L40: // QL
    if (l != lend) {
        for (m = l; m <= lend - 1; ++m) {
            tst = FMUL(eget(m - 1), eget(m - 1));
            if (tst <= FADD(FMUL(FMUL(eps2, fabsf(dget(m - 1))), fabsf(dget(m))), safmin)) goto L60;
        }
    }
    m = lend;
L60:
    if (m < lend) eset(m - 1, 0.f);
    p = dget(l - 1);
    if (m == l) goto L80;
    if (m == l + 1) {
        slaev2f(dget(l - 1), eget(l - 1), dget(l), &rt1, &rt2, &c, &s);
        wcset(l - 1, c); wsset(l - 1, s);
        slasr_bL(l, 2);
        dset(l - 1, rt1); dset(l, rt2); eset(l - 1, 0.f);
        l += 2;
        if (l <= lend) goto L40;
        goto L140;
    }
    if (jtot == nmaxit) goto L140;
    jtot++;
    g = FDIV(FSUB(dget(l), p), FMUL(2.f, eget(l - 1)));
    r = slapy2f(g, 1.f);
    g = FADD(FSUB(dget(m - 1), p), FDIV(eget(l - 1), FADD(g, f_sign(r, g))));
    s = 1.f; c = 1.f; p = 0.f;
    for (i = m - 1; i >= l; --i) {
        f  = FMUL(s, eget(i - 1));
        bb = FMUL(c, eget(i - 1));
        slartgf(g, f, &c, &s, &r);
        if (i != m - 1) eset(i, r);
        g = FSUB(dget(i), p);
        r = FADD(FMUL(FSUB(dget(i - 1), g), s), FMUL(FMUL(2.f, c), bb));
        p = FMUL(s, r);
        dset(i, FADD(g, p));
        g = FSUB(FMUL(c, r), bb);
        wcset(i - 1, c); wsset(i - 1, -s);
    }
    slasr_bL(l, m - l + 1);
    dset(l - 1, FSUB(dget(l - 1), p));
    eset(l - 1, g);
    goto L40;
L80:
    dset(l - 1, p);
    l++;
    if (l <= lend) goto L40;
    goto L140;

L90: // QR
    if (l != lend) {
        for (m = l; m >= lend + 1; --m) {
            tst = FMUL(eget(m - 2), eget(m - 2));
            if (tst <= FADD(FMUL(FMUL(eps2, fabsf(dget(m - 1))), fabsf(dget(m - 2))), safmin)) goto L110;
        }
    }
    m = lend;
L110:
    if (m > lend) eset(m - 2, 0.f);
    p = dget(l - 1);
    if (m == l) goto L130;
    if (m == l - 1) {
        slaev2f(dget(l - 2), eget(l - 2), dget(l - 1), &rt1, &rt2, &c, &s);
        wcset(m - 1, c); wsset(m - 1, s);
        slasr_fL(l - 1, 2);
        dset(l - 2, rt1); dset(l - 1, rt2); eset(l - 2, 0.f);
        l -= 2;
        if (l >= lend) goto L90;
        goto L140;
    }
    if (jtot == nmaxit) goto L140;
    jtot++;
    g = FDIV(FSUB(dget(l - 2), p), FMUL(2.f, eget(l - 2)));
    r = slapy2f(g, 1.f);
    g = FADD(FSUB(dget(m - 1), p), FDIV(eget(l - 2), FADD(g, f_sign(r, g))));
    s = 1.f; c = 1.f; p = 0.f;
    for (i = m; i <= l - 1; ++i) {
        f  = FMUL(s, eget(i - 1));
        bb = FMUL(c, eget(i - 1));
        slartgf(g, f, &c, &s, &r);
        if (i != m) eset(i - 2, r);
        g = FSUB(dget(i - 1), p);
        r = FADD(FMUL(FSUB(dget(i), g), s), FMUL(FMUL(2.f, c), bb));
        p = FMUL(s, r);
        dset(i - 1, FADD(g, p));
        g = FSUB(FMUL(c, r), bb);
        wcset(i - 1, c); wsset(i - 1, s);
    }
    slasr_fL(m, l - m + 1);
    dset(l - 1, FSUB(dget(l - 1), p));
    eset(l - 2, g);
    goto L90;
L130:
    dset(l - 1, p);
    l--;
    if (l >= lend) goto L90;
    goto L140;

L140:
    if (jtot < nmaxit) goto L10;
    goto L160;

L160:
    {
        auto swapcol = [&](int c1, int c2) {
            float t;
            if (c1 == 0 && c2 == 1) {
                t = za0; za0 = zb0; zb0 = t;
                t = za1; za1 = zb1; zb1 = t;
                t = za2; za2 = zb2; zb2 = t;
            } else if (c1 == 0) {
                t = za0; za0 = zc0; zc0 = t;
                t = za1; za1 = zc1; zc1 = t;
                t = za2; za2 = zc2; zc2 = t;
            } else {
                t = zb0; zb0 = zc0; zc0 = t;
                t = zb1; zb1 = zc1; zc1 = t;
                t = zb2; zb2 = zc2; zc2 = t;
            }
        };
        for (int ii = 2; ii <= 3; ++ii) {
            int ia = ii - 1, k = ia;
            float pp = dget(ia - 1);
            for (int j = ii; j <= 3; ++j)
                if (dget(j - 1) < pp) { k = j; pp = dget(j - 1); }
            if (k != ia) {
                dset(k - 1, dget(ia - 1)); dset(ia - 1, pp);
                swapcol(ia - 1, k - 1);
            }
        }
    }
}

__device__ void smallest_eigvec3(float a11, float a21, float a31,
                                 float a22, float a32, float a33,
                                 float* nrm) {
    float alpha = a21;
    float xnorm = fabsf(a31);
    float tau1, v3, eh;
    if (xnorm == 0.f) {
        tau1 = 0.f; eh = alpha; v3 = 0.f;
    } else {
        float beta = -f_sign(slapy2f(alpha, xnorm), alpha);
        tau1 = FDIV(FSUB(beta, alpha), beta);
        v3   = FMUL(a31, FDIV(1.f, FSUB(alpha, beta)));
        eh   = beta;
    }
    if (tau1 != 0.f) {
        float x1 = FMUL(tau1, FADD(a22, FMUL(a32, v3)));
        float x2 = FMUL(tau1, FADD(a32, FMUL(a33, v3)));
        float al = FMUL(FMUL(-0.5f, tau1), FADD(x1, FMUL(x2, v3)));
        float w1 = FADD(x1, al);
        float w2 = FADD(x2, FMUL(al, v3));
        a22 = FSUB(a22, FMUL(2.f, w1));
        a32 = FSUB(a32, FADD(FMUL(v3, w1), w2));
        a33 = FSUB(a33, FMUL(2.f, FMUL(v3, w2)));
    }
    float d0 = a11, d1 = a22, d2 = a33;
    float e0 = eh, e1 = a32;
    float za0 = 1.f, za1 = 0.f, za2 = 0.f;
    float zb0 = 0.f, zb1 = 1.f, zb2 = 0.f;
    float zc0 = 0.f, zc1 = 0.f, zc2 = 1.f;

    ssteqr3_reg(d0, d1, d2, e0, e1,
                za0, za1, za2, zb0, zb1, zb2, zc0, zc1, zc2);

    float z0 = za0, z1 = za1, z2 = za2;
    if (tau1 != 0.f) {
        float t = FMUL(tau1, FADD(z1, FMUL(v3, z2)));
        z1 = FSUB(z1, t);
        z2 = FSUB(z2, FMUL(t, v3));
    }
    nrm[0] = z0; nrm[1] = z1; nrm[2] = z2;
}

// ---------------------------------------------------------------------------
// Kernel A: kNN via warp-distributed global top-list. One warp per point.
// The current global top-11 (unique u64 keys (sq_bits<<32)|j) lives one slot
// per lane, sorted ascending across lanes; lane 10's key = live threshold,
// replicated in `worst`. Inserts are warp-parallel (ballot+popc+shfl_up).
// Passers processed in increasing j order with re-check => result is exactly
// sequential insertion over j=0..2047 == top_k's stable (sq, idx) order.
// Covariance + eigensolver warp-uniform; lane 0 writes SoA.
// ---------------------------------------------------------------------------
__global__ void __launch_bounds__(256)
knn_normals_kernel(const float* __restrict__ pts, float* __restrict__ soa) {
    __shared__ float sx[NPTS], sy[NPTS], sz[NPTS];
    int tid = threadIdx.x;
    for (int j = tid; j < NPTS; j += 256) {
        sx[j] = pts[j * 3 + 0];
        sy[j] = pts[j * 3 + 1];
        sz[j] = pts[j * 3 + 2];
    }
    __syncthreads();

    int warp = tid >> 5, lane = tid & 31;
    int p = blockIdx.x * 8 + warp;

    float pix = sx[p], piy = sy[p], piz = sz[p];

    unsigned long long vkey  = 0xFFFFFFFFFFFFFFFFull;   // my slot of the list
    unsigned long long worst = 0xFFFFFFFFFFFFFFFFull;   // slot 10 (replicated)

    for (int s = 0; s < NPTS / 32; ++s) {
        int j = s * 32 + lane;
        float dx = FSUB(pix, sx[j]);
        float dy = FSUB(piy, sy[j]);
        float dz = FSUB(piz, sz[j]);
        float sq = FADD(FADD(FMUL(dx, dx), FMUL(dy, dy)), FMUL(dz, dz));
        unsigned long long key =
            ((unsigned long long)__float_as_uint(sq) << 32) | (unsigned)j;

        unsigned pass = __ballot_sync(FULLM, key < worst);
        while (pass) {                    // warp-uniform loop (pass replicated)
            int src = __ffs(pass) - 1;
            pass &= pass - 1;
            unsigned long long k2 = __shfl_sync(FULLM, key, src);
            if (k2 < worst) {             // uniform: k2, worst replicated
                unsigned bal = __ballot_sync(FULLM, vkey < k2);
                int pos = __popc(bal);    // insertion index (keys unique)
                unsigned long long up = __shfl_up_sync(FULLM, vkey, 1);
                vkey = (lane < pos) ? vkey : ((lane == pos) ? k2 : up);
                worst = __shfl_sync(FULLM, vkey, KNN);   // slot 10
            }
        }
    }

    // slots 1..10 = the 10 neighbors (slot 0 = self, dropped as knn[:,1:])
    int nbr[KNN];
    #pragma unroll
    for (int k = 0; k < KNN; ++k)
        nbr[k] = (int)(unsigned)(__shfl_sync(FULLM, vkey, k + 1) & 0xFFFFFFFFull);

    // covariance + eigensolver: warp-uniform (smem broadcast reads, zero
    // divergence); lane 0 writes.
    float nx[KNN], ny[KNN], nz[KNN];
    float mx = 0.f, my = 0.f, mz = 0.f;
    #pragma unroll
    for (int k = 0; k < KNN; ++k) {
        int j = nbr[k];
        nx[k] = sx[j]; ny[k] = sy[j]; nz[k] = sz[j];
        mx = FADD(mx, nx[k]); my = FADD(my, ny[k]); mz = FADD(mz, nz[k]);
    }
    mx = FDIV(mx, 10.f); my = FDIV(my, 10.f); mz = FDIV(mz, 10.f);

    float c00 = 0.f, c10 = 0.f, c20 = 0.f, c11 = 0.f, c21 = 0.f, c22 = 0.f;
    #pragma unroll
    for (int k = 0; k < KNN; ++k) {
        float cx = FSUB(nx[k], mx);
        float cy = FSUB(ny[k], my);
        float cz = FSUB(nz[k], mz);
        c00 = FADD(c00, FMUL(cx, cx));
        c10 = FADD(c10, FMUL(cy, cx));
        c20 = FADD(c20, FMUL(cz, cx));
        c11 = FADD(c11, FMUL(cy, cy));
        c21 = FADD(c21, FMUL(cz, cy));
        c22 = FADD(c22, FMUL(cz, cz));
    }
    c00 = FDIV(c00, 10.f); c10 = FDIV(c10, 10.f); c20 = FDIV(c20, 10.f);
    c11 = FDIV(c11, 10.f); c21 = FDIV(c21, 10.f); c22 = FDIV(c22, 10.f);

    float nrm[3];
    smallest_eigvec3(c00, c10, c20, c11, c21, c22, nrm);

    if (lane == 0) {
        soa[p]            = pix;
        soa[NPTS + p]     = piy;
        soa[2 * NPTS + p] = piz;
        soa[3 * NPTS + p] = nrm[0];
        soa[4 * NPTS + p] = nrm[1];
        soa[5 * NPTS + p] = nrm[2];
        soa[6 * NPTS + p] = nrm[0] * nrm[0] + nrm[1] * nrm[1] + nrm[2] * nrm[2];
    }
}

// ---------------------------------------------------------------------------
// Fast atan2 for y >= 0 (result in [0, pi]); cephes coefficients, ~1e-7 abs err
// ---------------------------------------------------------------------------
__device__ __forceinline__ float fast_atan2_pos(float y, float x) {
    const float PI    = 3.14159265358979323846f;
    const float PIO2  = 1.57079632679489661923f;
    const float PIO4  = 0.78539816339744830962f;
    const float TAN8  = 0.41421356237309504880f;

    float ax = fabsf(x);
    float mn = fminf(y, ax), mx = fmaxf(y, ax);
    float t = (mx == 0.f) ? 0.f : __fdividef(mn, mx);

    float add = 0.f;
    if (t > TAN8) { t = __fdividef(t - 1.f, t + 1.f); add = PIO4; }

    float z = t * t;
    float p = 8.05374449538e-2f;
    p = p * z - 1.38776856032e-1f;
    p = p * z + 1.99777106478e-1f;
    p = p * z - 3.33329491539e-1f;
    float r = fmaf(p * z, t, t) + add;

    if (y > ax)  r = PIO2 - r;
    if (x < 0.f) r = PI - r;
    return r;
}

__device__ __forceinline__ void ppf_pair(
    float pix, float piy, float piz, float nix, float niy, float niz, float nis,
    float pjx, float pjy, float pjz, float njx, float njy, float njz, float njs,
    float& dn, float& a1, float& a2, float& a3)
{
    float dx = pix - pjx, dy = piy - pjy, dz = piz - pjz;
    float sq = dx * dx + dy * dy + dz * dz;
    dn = (sq > 0.f) ? sq * rsqrtf(sq) : 0.f;

    float dot1 = nix * dx + niy * dy + niz * dz;
    float csq1 = fmaf(nis, sq, -(dot1 * dot1));
    float cn1  = (csq1 > 0.f) ? csq1 * rsqrtf(csq1) : 0.f;
    a1 = fast_atan2_pos(cn1, dot1);

    float dot2 = njx * dx + njy * dy + njz * dz;
    float csq2 = fmaf(njs, sq, -(dot2 * dot2));
    float cn2  = (csq2 > 0.f) ? csq2 * rsqrtf(csq2) : 0.f;
    a2 = fast_atan2_pos(cn2, dot2);

    float dot3 = nix * njx + niy * njy + niz * njz;
    float csq3 = fmaf(nis, njs, -(dot3 * dot3));
    float cn3  = (csq3 > 0.f) ? csq3 * rsqrtf(csq3) : 0.f;
    a3 = fast_atan2_pos(cn3, dot3);
}

// ---------------------------------------------------------------------------
// Kernel B: symmetric PPF. TWO warps per unordered 32x32 tile pair, in the
// SAME block; half 1 posts partials to smem, half 0 combines + writes.
// F(j,i) = [dn, pi - a2(i,j), pi - a1(i,j), a3] (exact identities).
// ---------------------------------------------------------------------------
__global__ void __launch_bounds__(256)
sym_ppf_kernel(const float* __restrict__ soa, float4* __restrict__ part) {
    const float PI = 3.14159265358979323846f;
    __shared__ float sbuf[4][32][9];

    int wid  = threadIdx.x >> 5;
    int ps   = wid >> 1;
    int sh   = wid & 1;
    int lane = threadIdx.x & 31;
    int wt   = blockIdx.x * 4 + ps;

    int A = (int)((sqrtf(8.f * (float)wt + 1.f) - 1.f) * 0.5f);
    while ((A + 1) * (A + 2) / 2 <= wt) ++A;
    while (A * (A + 1) / 2 > wt) --A;
    int B = wt - A * (A + 1) / 2;

    const float* px = soa;
    const float* py = soa + NPTS;
    const float* pz = soa + 2 * NPTS;
    const float* nx = soa + 3 * NPTS;
    const float* ny = soa + 4 * NPTS;
    const float* nz = soa + 5 * NPTS;
    const float* ns = soa + 6 * NPTS;

    int ri = B * 32 + lane;
    int rj = A * 32 + lane;
    float pix = __ldg(&px[ri]), piy = __ldg(&py[ri]), piz = __ldg(&pz[ri]);
    float nix = __ldg(&nx[ri]), niy = __ldg(&ny[ri]), niz = __ldg(&nz[ri]);
    float nis = __ldg(&ns[ri]);
    float qjx = __ldg(&px[rj]), qjy = __ldg(&py[rj]), qjz = __ldg(&pz[rj]);
    float mjx = __ldg(&nx[rj]), mjy = __ldg(&ny[rj]), mjz = __ldg(&nz[rj]);
    float mjs = __ldg(&ns[rj]);

    float ai0 = 0.f, ai1 = 0.f, ai2 = 0.f, ai3 = 0.f;
    float aj0 = 0.f, aj1 = 0.f, aj2 = 0.f, aj3 = 0.f;
    int s0i = sh * 16;

    if (A != B) {
        #pragma unroll 4
        for (int s = s0i; s < s0i + 16; ++s) {
            int src = (lane + s) & 31;
            float pjx = __shfl_sync(FULLM, qjx, src);
            float pjy = __shfl_sync(FULLM, qjy, src);
            float pjz = __shfl_sync(FULLM, qjz, src);
            float njx = __shfl_sync(FULLM, mjx, src);
            float njy = __shfl_sync(FULLM, mjy, src);
            float njz = __shfl_sync(FULLM, mjz, src);
            float njs = __shfl_sync(FULLM, mjs, src);

            float dn, a1, a2, a3;
            ppf_pair(pix, piy, piz, nix, niy, niz, nis,
                     pjx, pjy, pjz, njx, njy, njz, njs, dn, a1, a2, a3);

            ai0 += dn; ai1 += a1; ai2 += a2; ai3 += a3;

            float c0 = dn, c1 = PI - a2, c2 = PI - a1, c3 = a3;
            int rsrc = (lane - s) & 31;
            aj0 += __shfl_sync(FULLM, c0, rsrc);
            aj1 += __shfl_sync(FULLM, c1, rsrc);
            aj2 += __shfl_sync(FULLM, c2, rsrc);
            aj3 += __shfl_sync(FULLM, c3, rsrc);
        }
    } else {
        #pragma unroll 4
        for (int s = s0i; s < s0i + 16; ++s) {
            int src = (lane + s) & 31;
            float pjx = __shfl_sync(FULLM, qjx, src);
            float pjy = __shfl_sync(FULLM, qjy, src);
            float pjz = __shfl_sync(FULLM, qjz, src);
            float njx = __shfl_sync(FULLM, mjx, src);
            float njy = __shfl_sync(FULLM, mjy, src);
            float njz = __shfl_sync(FULLM, mjz, src);
            float njs = __shfl_sync(FULLM, mjs, src);

            float dn, a1, a2, a3;
            ppf_pair(pix, piy, piz, nix, niy, niz, nis,
                     pjx, pjy, pjz, njx, njy, njz, njs, dn, a1, a2, a3);

            ai0 += dn; ai1 += a1; ai2 += a2; ai3 += a3;
        }
    }

    if (sh == 1) {
        sbuf[ps][lane][0] = ai0; sbuf[ps][lane][1] = ai1;
        sbuf[ps][lane][2] = ai2; sbuf[ps][lane][3] = ai3;
        sbuf[ps][lane][4] = aj0; sbuf[ps][lane][5] = aj1;
        sbuf[ps][lane][6] = aj2; sbuf[ps][lane][7] = aj3;
    }
    __syncthreads();
    if (sh == 0) {
        ai0 += sbuf[ps][lane][0]; ai1 += sbuf[ps][lane][1];
        ai2 += sbuf[ps][lane][2]; ai3 += sbuf[ps][lane][3];
        aj0 += sbuf[ps][lane][4]; aj1 += sbuf[ps][lane][5];
        aj2 += sbuf[ps][lane][6]; aj3 += sbuf[ps][lane][7];

        part[ri * NTILES + A] = make_float4(ai0, ai1, ai2, ai3);
        if (A != B)
            part[rj * NTILES + B] = make_float4(aj0, aj1, aj2, aj3);
    }
}

// ---------------------------------------------------------------------------
// Kernel C: tree-reduce 64 partials per row + 4->256 linear layer
// ---------------------------------------------------------------------------
__global__ void __launch_bounds__(256)
finalize_kernel(const float4* __restrict__ part,
                const float* __restrict__ W, const float* __restrict__ b,
                float* __restrict__ out) {
    __shared__ float4 wsum[2];
    __shared__ float feat[4];
    int i = blockIdx.x, t = threadIdx.x;

    if (t < 64) {
        float4 v = part[i * NTILES + t];
        #pragma unroll
        for (int off = 16; off > 0; off >>= 1) {
            v.x += __shfl_down_sync(FULLM, v.x, off);
            v.y += __shfl_down_sync(FULLM, v.y, off);
            v.z += __shfl_down_sync(FULLM, v.z, off);
            v.w += __shfl_down_sync(FULLM, v.w, off);
        }
        if ((t & 31) == 0) wsum[t >> 5] = v;
    }
    __syncthreads();
    if (t == 0) {
        float4 a = wsum[0], c = wsum[1];
        feat[0] = (a.x + c.x) / 2048.f;
        feat[1] = (a.y + c.y) / 2048.f;
        feat[2] = (a.z + c.z) / 2048.f;
        feat[3] = (a.w + c.w) / 2048.f;
    }
    __syncthreads();
    float f0 = feat[0], f1 = feat[1], f2 = feat[2], f3 = feat[3];
    float acc = f0 * W[t * 4 + 0];
    acc = acc + f1 * W[t * 4 + 1];
    acc = acc + f2 * W[t * 4 + 2];
    acc = acc + f3 * W[t * 4 + 3];
    acc = acc + b[t];
    out[i * OUTF + t] = acc;
}

extern "C" void kernel_launch(void* const* d_in, const int* in_sizes, int n_in,
                              void* d_out, int out_size) {
    const float* points = (const float*)d_in[0];   // (1, 2048, 3)
    const float* W      = (const float*)d_in[1];   // (256, 4)
    const float* b      = (const float*)d_in[2];   // (256,)
    float* out          = (float*)d_out;           // (1, 2048, 256)
    (void)in_sizes; (void)n_in; (void)out_size;

    float* soa; float4* part;
    cudaGetSymbolAddress((void**)&soa, g_soa);
    cudaGetSymbolAddress((void**)&part, g_part);

    knn_normals_kernel<<<NPTS / 8, 256>>>(points, soa);
    sym_ppf_kernel<<<NTPAIRS / 4, 256>>>(soa, part);
    finalize_kernel<<<NPTS, 256>>>(part, W, b, out);
}

// round 15
// speedup vs baseline: 1.5643x; 1.0236x over previous
#include <cuda_runtime.h>
#include <cuda_bf16.h>
#include <math.h>
#include <float.h>

#define NPTS 2048
#define KNN  10
#define OUTF 256
#define NTILES 64                 // 2048 / 32
#define NTPAIRS 2080              // 64*65/2  (= 520 blocks * 4 pairs exactly)
#define FULLM 0xFFFFFFFFu
#define KMAX  0xFFFFFFFFFFFFFFFFull

// _rn intrinsics: immune to compiler fast-math; used on all eigen/kNN-critical math
#define FMUL(a,b)  __fmul_rn((a),(b))
#define FADD(a,b)  __fadd_rn((a),(b))
#define FSUB(a,b)  __fsub_rn((a),(b))
#define FDIV(a,b)  __fdiv_rn((a),(b))
#define FSQRT(a)   __fsqrt_rn((a))

// SoA: [0..N)=px [N..2N)=py [2N..3N)=pz [3N..4N)=nx [4N..5N)=ny [5N..6N)=nz [6N..7N)=|n|^2
__device__ float  g_soa[NPTS * 7];
// per-(row, col-tile) partial PPF sums; single writer per slot (deterministic)
__device__ float4 g_part[NPTS * NTILES];

// ---------------------------------------------------------------------------
// LAPACK fp32 building blocks (netlib-faithful, LAPACK >= 3.10 conventions)
// ---------------------------------------------------------------------------

__device__ __forceinline__ float f_sign(float a, float b) {
    return (b >= 0.f) ? fabsf(a) : -fabsf(a);
}

__device__ __forceinline__ float slapy2f(float x, float y) {
    float xa = fabsf(x), ya = fabsf(y);
    float w = fmaxf(xa, ya), z = fminf(xa, ya);
    if (z == 0.f) return w;
    float t = FDIV(z, w);
    return FMUL(w, FSQRT(FADD(1.f, FMUL(t, t))));
}

__device__ __forceinline__ void slartgf(float f, float g, float* c, float* s, float* r) {
    if (g == 0.f)      { *c = 1.f; *s = 0.f; *r = f; }
    else if (f == 0.f) { *c = 0.f; *s = (g >= 0.f) ? 1.f : -1.f; *r = fabsf(g); }
    else {
        float d  = FSQRT(FADD(FMUL(f, f), FMUL(g, g)));
        float rr = (f >= 0.f) ? d : -d;
        *c = FDIV(fabsf(f), d);
        *s = FDIV(g, rr);
        *r = rr;
    }
}

__device__ void slaev2f(float a, float b, float c,
                        float* rt1, float* rt2, float* cs1, float* sn1) {
    float sm  = FADD(a, c);
    float df  = FSUB(a, c);
    float adf = fabsf(df);
    float tb  = FADD(b, b);
    float ab  = fabsf(tb);
    float acmx, acmn;
    if (fabsf(a) > fabsf(c)) { acmx = a; acmn = c; } else { acmx = c; acmn = a; }
    float rt;
    if (adf > ab) {
        float t = FDIV(ab, adf);
        rt = FMUL(adf, FSQRT(FADD(1.f, FMUL(t, t))));
    } else if (adf < ab) {
        float t = FDIV(adf, ab);
        rt = FMUL(ab, FSQRT(FADD(1.f, FMUL(t, t))));
    } else {
        rt = FMUL(ab, FSQRT(2.f));
    }
    int sgn1;
    if (sm < 0.f) {
        *rt1 = FMUL(0.5f, FSUB(sm, rt)); sgn1 = -1;
        *rt2 = FSUB(FMUL(FDIV(acmx, *rt1), acmn), FMUL(FDIV(b, *rt1), b));
    } else if (sm > 0.f) {
        *rt1 = FMUL(0.5f, FADD(sm, rt)); sgn1 = 1;
        *rt2 = FSUB(FMUL(FDIV(acmx, *rt1), acmn), FMUL(FDIV(b, *rt1), b));
    } else {
        *rt1 = FMUL(0.5f, rt); *rt2 = FMUL(-0.5f, rt); sgn1 = 1;
    }
    float cs; int sgn2;
    if (df >= 0.f) { cs = FADD(df, rt); sgn2 =  1; }
    else           { cs = FSUB(df, rt); sgn2 = -1; }
    float acs = fabsf(cs);
    if (acs > ab) {
        float ct = FDIV(-tb, cs);
        *sn1 = FDIV(1.f, FSQRT(FADD(1.f, FMUL(ct, ct))));
        *cs1 = FMUL(ct, *sn1);
    } else {
        if (ab == 0.f) { *cs1 = 1.f; *sn1 = 0.f; }
        else {
            float tn = FDIV(-cs, tb);
            *cs1 = FDIV(1.f, FSQRT(FADD(1.f, FMUL(tn, tn))));
            *sn1 = FMUL(tn, *cs1);
        }
    }
    if (sgn1 == sgn2) { float tn = *cs1; *cs1 = -(*sn1); *sn1 = tn; }
}

// ssteqr('I', n=3), register-resident; control flow/arithmetic == netlib
__device__ void ssteqr3_reg(float& d0, float& d1, float& d2,
                            float& e0, float& e1,
                            float& za0, float& za1, float& za2,
                            float& zb0, float& zb1, float& zb2,
                            float& zc0, float& zc1, float& zc2) {
    const float eps    = 5.9604645e-8f;
    const float eps2   = eps * eps;
    const float safmin = 1.17549435e-38f;
    float wc0 = 0.f, wc1 = 0.f, ws0 = 0.f, ws1 = 0.f;

    auto dget = [&](int i) -> float { return i == 0 ? d0 : (i == 1 ? d1 : d2); };
    auto dset = [&](int i, float v) { if (i == 0) d0 = v; else if (i == 1) d1 = v; else d2 = v; };
    auto eget = [&](int i) -> float { return i == 0 ? e0 : e1; };
    auto eset = [&](int i, float v) { if (i == 0) e0 = v; else e1 = v; };
    auto wcget = [&](int i) -> float { return i == 0 ? wc0 : wc1; };
    auto wcset = [&](int i, float v) { if (i == 0) wc0 = v; else wc1 = v; };
    auto wsget = [&](int i) -> float { return i == 0 ? ws0 : ws1; };
    auto wsset = [&](int i, float v) { if (i == 0) ws0 = v; else ws1 = v; };

    auto rot = [&](int cb1, float c, float s) {
        if (cb1 == 1) {
            float t;
            t = zb0; zb0 = FSUB(FMUL(c, t), FMUL(s, za0)); za0 = FADD(FMUL(s, t), FMUL(c, za0));
            t = zb1; zb1 = FSUB(FMUL(c, t), FMUL(s, za1)); za1 = FADD(FMUL(s, t), FMUL(c, za1));
            t = zb2; zb2 = FSUB(FMUL(c, t), FMUL(s, za2)); za2 = FADD(FMUL(s, t), FMUL(c, za2));
        } else {
            float t;
            t = zc0; zc0 = FSUB(FMUL(c, t), FMUL(s, zb0)); zb0 = FADD(FMUL(s, t), FMUL(c, zb0));
            t = zc1; zc1 = FSUB(FMUL(c, t), FMUL(s, zb1)); zb1 = FADD(FMUL(s, t), FMUL(c, zb1));
            t = zc2; zc2 = FSUB(FMUL(c, t), FMUL(s, zb2)); zb2 = FADD(FMUL(s, t), FMUL(c, zb2));
        }
    };
    auto slasr_bL = [&](int lcol, int mm) {
        for (int j = mm - 1; j >= 1; --j) {
            float c = wcget(lcol - 2 + j), s = wsget(lcol - 2 + j);
            if (c != 1.f || s != 0.f) rot(lcol + j - 1, c, s);
        }
    };
    auto slasr_fL = [&](int lcol, int mm) {
        for (int j = 1; j <= mm - 1; ++j) {
            float c = wcget(lcol - 2 + j), s = wsget(lcol - 2 + j);
            if (c != 1.f || s != 0.f) rot(lcol + j - 1, c, s);
        }
    };

    int l1, l, lsv, lend, lendsv, m, i, jtot, nmaxit;
    float p, g, r, s, c, f, bb, rt1, rt2, anorm, tst;
    nmaxit = 90; jtot = 0; l1 = 1;

L10:
    if (l1 > 3) goto L160;
    if (l1 > 1) eset(l1 - 2, 0.f);
    if (l1 <= 2) {
        for (m = l1; m <= 2; ++m) {
            tst = fabsf(eget(m - 1));
            if (tst == 0.f) goto L30;
            if (tst <= FMUL(FMUL(FSQRT(fabsf(dget(m - 1))), FSQRT(fabsf(dget(m)))), eps)) {
                eset(m - 1, 0.f); goto L30;
            }
        }
    }
    m = 3;
L30:
    l = l1; lsv = l; lend = m; lendsv = lend; l1 = m + 1;
    if (lend == l) goto L10;
    anorm = 0.f;
    for (i = l; i <= lend; ++i)     anorm = fmaxf(anorm, fabsf(dget(i - 1)));
    for (i = l; i <= lend - 1; ++i) anorm = fmaxf(anorm, fabsf(eget(i - 1)));
    if (anorm == 0.f) goto L10;
    if (fabsf(dget(lend - 1)) < fabsf(dget(l - 1))) { lend = lsv; l = lendsv; }
    if (lend > l) goto L40; else goto L90;

L40: // QL
    if (l != lend) {
        for (m = l; m <= lend - 1; ++m) {
            tst = FMUL(eget(m - 1), eget(m - 1));
            if (tst <= FADD(FMUL(FMUL(eps2, fabsf(dget(m - 1))), fabsf(dget(m))), safmin)) goto L60;
        }
    }
    m = lend;
L60:
    if (m < lend) eset(m - 1, 0.f);
    p = dget(l - 1);
    if (m == l) goto L80;
    if (m == l + 1) {
        slaev2f(dget(l - 1), eget(l - 1), dget(l), &rt1, &rt2, &c, &s);
        wcset(l - 1, c); wsset(l - 1, s);
        slasr_bL(l, 2);
        dset(l - 1, rt1); dset(l, rt2); eset(l - 1, 0.f);
        l += 2;
        if (l <= lend) goto L40;
        goto L140;
    }
    if (jtot == nmaxit) goto L140;
    jtot++;
    g = FDIV(FSUB(dget(l), p), FMUL(2.f, eget(l - 1)));
    r = slapy2f(g, 1.f);
    g = FADD(FSUB(dget(m - 1), p), FDIV(eget(l - 1), FADD(g, f_sign(r, g))));
    s = 1.f; c = 1.f; p = 0.f;
    for (i = m - 1; i >= l; --i) {
        f  = FMUL(s, eget(i - 1));
        bb = FMUL(c, eget(i - 1));
        slartgf(g, f, &c, &s, &r);
        if (i != m - 1) eset(i, r);
        g = FSUB(dget(i), p);
        r = FADD(FMUL(FSUB(dget(i - 1), g), s), FMUL(FMUL(2.f, c), bb));
        p = FMUL(s, r);
        dset(i, FADD(g, p));
        g = FSUB(FMUL(c, r), bb);
        wcset(i - 1, c); wsset(i - 1, -s);
    }
    slasr_bL(l, m - l + 1);
    dset(l - 1, FSUB(dget(l - 1), p));
    eset(l - 1, g);
    goto L40;
L80:
    dset(l - 1, p);
    l++;
    if (l <= lend) goto L40;
    goto L140;

L90: // QR
    if (l != lend) {
        for (m = l; m >= lend + 1; --m) {
            tst = FMUL(eget(m - 2), eget(m - 2));
            if (tst <= FADD(FMUL(FMUL(eps2, fabsf(dget(m - 1))), fabsf(dget(m - 2))), safmin)) goto L110;
        }
    }
    m = lend;
L110:
    if (m > lend) eset(m - 2, 0.f);
    p = dget(l - 1);
    if (m == l) goto L130;
    if (m == l - 1) {
        slaev2f(dget(l - 2), eget(l - 2), dget(l - 1), &rt1, &rt2, &c, &s);
        wcset(m - 1, c); wsset(m - 1, s);
        slasr_fL(l - 1, 2);
        dset(l - 2, rt1); dset(l - 1, rt2); eset(l - 2, 0.f);
        l -= 2;
        if (l >= lend) goto L90;
        goto L140;
    }
    if (jtot == nmaxit) goto L140;
    jtot++;
    g = FDIV(FSUB(dget(l - 2), p), FMUL(2.f, eget(l - 2)));
    r = slapy2f(g, 1.f);
    g = FADD(FSUB(dget(m - 1), p), FDIV(eget(l - 2), FADD(g, f_sign(r, g))));
    s = 1.f; c = 1.f; p = 0.f;
    for (i = m; i <= l - 1; ++i) {
        f  = FMUL(s, eget(i - 1));
        bb = FMUL(c, eget(i - 1));
        slartgf(g, f, &c, &s, &r);
        if (i != m) eset(i - 2, r);
        g = FSUB(dget(i - 1), p);
        r = FADD(FMUL(FSUB(dget(i), g), s), FMUL(FMUL(2.f, c), bb));
        p = FMUL(s, r);
        dset(i - 1, FADD(g, p));
        g = FSUB(FMUL(c, r), bb);
        wcset(i - 1, c); wsset(i - 1, s);
    }
    slasr_fL(m, l - m + 1);
    dset(l - 1, FSUB(dget(l - 1), p));
    eset(l - 2, g);
    goto L90;
L130:
    dset(l - 1, p);
    l--;
    if (l >= lend) goto L90;
    goto L140;

L140:
    if (jtot < nmaxit) goto L10;
    goto L160;

L160:
    {
        auto swapcol = [&](int c1, int c2) {
            float t;
            if (c1 == 0 && c2 == 1) {
                t = za0; za0 = zb0; zb0 = t;
                t = za1; za1 = zb1; zb1 = t;
                t = za2; za2 = zb2; zb2 = t;
            } else if (c1 == 0) {
                t = za0; za0 = zc0; zc0 = t;
                t = za1; za1 = zc1; zc1 = t;
                t = za2; za2 = zc2; zc2 = t;
            } else {
                t = zb0; zb0 = zc0; zc0 = t;
                t = zb1; zb1 = zc1; zc1 = t;
                t = zb2; zb2 = zc2; zc2 = t;
            }
        };
        for (int ii = 2; ii <= 3; ++ii) {
            int ia = ii - 1, k = ia;
            float pp = dget(ia - 1);
            for (int j = ii; j <= 3; ++j)
                if (dget(j - 1) < pp) { k = j; pp = dget(j - 1); }
            if (k != ia) {
                dset(k - 1, dget(ia - 1)); dset(ia - 1, pp);
                swapcol(ia - 1, k - 1);
            }
        }
    }
}

__device__ void smallest_eigvec3(float a11, float a21, float a31,
                                 float a22, float a32, float a33,
                                 float* nrm) {
    float alpha = a21;
    float xnorm = fabsf(a31);
    float tau1, v3, eh;
    if (xnorm == 0.f) {
        tau1 = 0.f; eh = alpha; v3 = 0.f;
    } else {
        float beta = -f_sign(slapy2f(alpha, xnorm), alpha);
        tau1 = FDIV(FSUB(beta, alpha), beta);
        v3   = FMUL(a31, FDIV(1.f, FSUB(alpha, beta)));
        eh   = beta;
    }
    if (tau1 != 0.f) {
        float x1 = FMUL(tau1, FADD(a22, FMUL(a32, v3)));
        float x2 = FMUL(tau1, FADD(a32, FMUL(a33, v3)));
        float al = FMUL(FMUL(-0.5f, tau1), FADD(x1, FMUL(x2, v3)));
        float w1 = FADD(x1, al);
        float w2 = FADD(x2, FMUL(al, v3));
        a22 = FSUB(a22, FMUL(2.f, w1));
        a32 = FSUB(a32, FADD(FMUL(v3, w1), w2));
        a33 = FSUB(a33, FMUL(2.f, FMUL(v3, w2)));
    }
    float d0 = a11, d1 = a22, d2 = a33;
    float e0 = eh, e1 = a32;
    float za0 = 1.f, za1 = 0.f, za2 = 0.f;
    float zb0 = 0.f, zb1 = 1.f, zb2 = 0.f;
    float zc0 = 0.f, zc1 = 0.f, zc2 = 1.f;

    ssteqr3_reg(d0, d1, d2, e0, e1,
                za0, za1, za2, zb0, zb1, zb2, zc0, zc1, zc2);

    float z0 = za0, z1 = za1, z2 = za2;
    if (tau1 != 0.f) {
        float t = FMUL(tau1, FADD(z1, FMUL(v3, z2)));
        z1 = FSUB(z1, t);
        z2 = FSUB(z2, FMUL(t, v3));
    }
    nrm[0] = z0; nrm[1] = z1; nrm[2] = z2;
}

// ascending bitonic sort of one u64 per lane across the warp
__device__ __forceinline__ unsigned long long warp_bitonic_sort_u64(
    unsigned long long val, int lane) {
    #pragma unroll
    for (int k = 2; k <= 32; k <<= 1) {
        #pragma unroll
        for (int j = k >> 1; j > 0; j >>= 1) {
            unsigned long long other = __shfl_xor_sync(FULLM, val, j);
            bool up = ((lane & k) == 0);
            bool lower = ((lane & j) == 0);
            bool keepMin = (lower == up);
            bool less = (val < other);
            val = (keepMin == less) ? val : other;
        }
    }
    return val;
}

// ---------------------------------------------------------------------------
// Kernel A: kNN, TWO warps per point. Each warp builds a distributed top-11
// (one sorted slot per lane; unique u64 keys (sq_bits<<32)|j) over its 1024
// candidates: bitonic init on the first batch, then threshold-filtered
// warp-parallel inserts. The two sorted 11-lists are rank-merged in smem;
// top-11 of the union == global top-11 in (sq, idx) order == top_k's stable
// order. Covariance + eigensolver warp-uniform on the even warp.
// ---------------------------------------------------------------------------
__global__ void __launch_bounds__(256)
knn_normals_kernel(const float* __restrict__ pts, float* __restrict__ soa) {
    __shared__ float sx[NPTS], sy[NPTS], sz[NPTS];
    __shared__ unsigned long long mbuf[4][22];   // per point-slot: 2 x 11 keys
    __shared__ unsigned long long mout[4][11];   // merged top-11 (sorted)
    int tid = threadIdx.x;
    for (int j = tid; j < NPTS; j += 256) {
        sx[j] = pts[j * 3 + 0];
        sy[j] = pts[j * 3 + 1];
        sz[j] = pts[j * 3 + 2];
    }
    __syncthreads();

    int warp = tid >> 5, lane = tid & 31;
    int wp   = warp >> 1;                 // point slot in block (0..3)
    int half = warp & 1;                  // candidate half
    int p    = blockIdx.x * 4 + wp;

    float pix = sx[p], piy = sy[p], piz = sz[p];
    int base = half * (NPTS / 2);

    // --- bitonic init on first batch ---
    {
        int j = base + lane;
        float dx = FSUB(pix, sx[j]);
        float dy = FSUB(piy, sy[j]);
        float dz = FSUB(piz, sz[j]);
        float sq = FADD(FADD(FMUL(dx, dx), FMUL(dy, dy)), FMUL(dz, dz));
        unsigned long long key =
            ((unsigned long long)__float_as_uint(sq) << 32) | (unsigned)j;
        key = warp_bitonic_sort_u64(key, lane);
        if (lane > KNN) key = KMAX;       // keep slots 0..10
        // (list stays sorted ascending; slots 11..31 = MAX)
        unsigned long long vkey = key;
        unsigned long long worst = __shfl_sync(FULLM, vkey, KNN);

        // --- scan remaining batches with threshold filter ---
        for (int s = 1; s < NPTS / 64; ++s) {
            int jj = base + s * 32 + lane;
            float ddx = FSUB(pix, sx[jj]);
            float ddy = FSUB(piy, sy[jj]);
            float ddz = FSUB(piz, sz[jj]);
            float ssq = FADD(FADD(FMUL(ddx, ddx), FMUL(ddy, ddy)), FMUL(ddz, ddz));
            unsigned long long k1 =
                ((unsigned long long)__float_as_uint(ssq) << 32) | (unsigned)jj;

            unsigned pass = __ballot_sync(FULLM, k1 < worst);
            while (pass) {                 // warp-uniform
                int src = __ffs(pass) - 1;
                pass &= pass - 1;
                unsigned long long k2 = __shfl_sync(FULLM, k1, src);
                if (k2 < worst) {
                    unsigned bal = __ballot_sync(FULLM, vkey < k2);
                    int pos = __popc(bal);
                    unsigned long long up = __shfl_up_sync(FULLM, vkey, 1);
                    vkey = (lane < pos) ? vkey : ((lane == pos) ? k2 : up);
                    worst = __shfl_sync(FULLM, vkey, KNN);
                }
            }
        }

        if (lane <= KNN) mbuf[wp][half * 11 + lane] = vkey;
    }
    __syncthreads();

    if (half == 0) {
        // rank-merge the 22 unique keys (rank = count of smaller keys)
        if (lane < 22) {
            unsigned long long mykey = mbuf[wp][lane];
            int rank = 0;
            #pragma unroll
            for (int m = 0; m < 22; ++m)
                rank += (mbuf[wp][m] < mykey) ? 1 : 0;
            if (rank <= KNN) mout[wp][rank] = mykey;
        }
        __syncwarp();

        // neighbors = merged slots 1..10 (slot 0 = self/minimal key, dropped)
        int nbr[KNN];
        #pragma unroll
        for (int k = 0; k < KNN; ++k)
            nbr[k] = (int)(unsigned)(mout[wp][k + 1] & 0xFFFFFFFFull);

        // covariance + eigensolver: warp-uniform; lane 0 writes
        float nx[KNN], ny[KNN], nz[KNN];
        float mx = 0.f, my = 0.f, mz = 0.f;
        #pragma unroll
        for (int k = 0; k < KNN; ++k) {
            int j = nbr[k];
            nx[k] = sx[j]; ny[k] = sy[j]; nz[k] = sz[j];
            mx = FADD(mx, nx[k]); my = FADD(my, ny[k]); mz = FADD(mz, nz[k]);
        }
        mx = FDIV(mx, 10.f); my = FDIV(my, 10.f); mz = FDIV(mz, 10.f);

        float c00 = 0.f, c10 = 0.f, c20 = 0.f, c11 = 0.f, c21 = 0.f, c22 = 0.f;
        #pragma unroll
        for (int k = 0; k < KNN; ++k) {
            float cx = FSUB(nx[k], mx);
            float cy = FSUB(ny[k], my);
            float cz = FSUB(nz[k], mz);
            c00 = FADD(c00, FMUL(cx, cx));
            c10 = FADD(c10, FMUL(cy, cx));
            c20 = FADD(c20, FMUL(cz, cx));
            c11 = FADD(c11, FMUL(cy, cy));
            c21 = FADD(c21, FMUL(cz, cy));
            c22 = FADD(c22, FMUL(cz, cz));
        }
        c00 = FDIV(c00, 10.f); c10 = FDIV(c10, 10.f); c20 = FDIV(c20, 10.f);
        c11 = FDIV(c11, 10.f); c21 = FDIV(c21, 10.f); c22 = FDIV(c22, 10.f);

        float nrm[3];
        smallest_eigvec3(c00, c10, c20, c11, c21, c22, nrm);

        if (lane == 0) {
            soa[p]            = pix;
            soa[NPTS + p]     = piy;
            soa[2 * NPTS + p] = piz;
            soa[3 * NPTS + p] = nrm[0];
            soa[4 * NPTS + p] = nrm[1];
            soa[5 * NPTS + p] = nrm[2];
            soa[6 * NPTS + p] = nrm[0] * nrm[0] + nrm[1] * nrm[1] + nrm[2] * nrm[2];
        }
    }
}

// ---------------------------------------------------------------------------
// Fast atan2 for y >= 0 (result in [0, pi]); cephes coefficients, ~1e-7 abs err
// ---------------------------------------------------------------------------
__device__ __forceinline__ float fast_atan2_pos(float y, float x) {
    const float PI    = 3.14159265358979323846f;
    const float PIO2  = 1.57079632679489661923f;
    const float PIO4  = 0.78539816339744830962f;
    const float TAN8  = 0.41421356237309504880f;

    float ax = fabsf(x);
    float mn = fminf(y, ax), mx = fmaxf(y, ax);
    float t = (mx == 0.f) ? 0.f : __fdividef(mn, mx);

    float add = 0.f;
    if (t > TAN8) { t = __fdividef(t - 1.f, t + 1.f); add = PIO4; }

    float z = t * t;
    float p = 8.05374449538e-2f;
    p = p * z - 1.38776856032e-1f;
    p = p * z + 1.99777106478e-1f;
    p = p * z - 3.33329491539e-1f;
    float r = fmaf(p * z, t, t) + add;

    if (y > ax)  r = PIO2 - r;
    if (x < 0.f) r = PI - r;
    return r;
}

__device__ __forceinline__ void ppf_pair(
    float pix, float piy, float piz, float nix, float niy, float niz, float nis,
    float pjx, float pjy, float pjz, float njx, float njy, float njz, float njs,
    float& dn, float& a1, float& a2, float& a3)
{
    float dx = pix - pjx, dy = piy - pjy, dz = piz - pjz;
    float sq = dx * dx + dy * dy + dz * dz;
    dn = (sq > 0.f) ? sq * rsqrtf(sq) : 0.f;

    float dot1 = nix * dx + niy * dy + niz * dz;
    float csq1 = fmaf(nis, sq, -(dot1 * dot1));
    float cn1  = (csq1 > 0.f) ? csq1 * rsqrtf(csq1) : 0.f;
    a1 = fast_atan2_pos(cn1, dot1);

    float dot2 = njx * dx + njy * dy + njz * dz;
    float csq2 = fmaf(njs, sq, -(dot2 * dot2));
    float cn2  = (csq2 > 0.f) ? csq2 * rsqrtf(csq2) : 0.f;
    a2 = fast_atan2_pos(cn2, dot2);

    float dot3 = nix * njx + niy * njy + niz * njz;
    float csq3 = fmaf(nis, njs, -(dot3 * dot3));
    float cn3  = (csq3 > 0.f) ? csq3 * rsqrtf(csq3) : 0.f;
    a3 = fast_atan2_pos(cn3, dot3);
}

// ---------------------------------------------------------------------------
// Kernel B: symmetric PPF. TWO warps per unordered 32x32 tile pair, in the
// SAME block; half 1 posts partials to smem, half 0 combines + writes.
// F(j,i) = [dn, pi - a2(i,j), pi - a1(i,j), a3] (exact identities).
// ---------------------------------------------------------------------------
__global__ void __launch_bounds__(256)
sym_ppf_kernel(const float* __restrict__ soa, float4* __restrict__ part) {
    const float PI = 3.14159265358979323846f;
    __shared__ float sbuf[4][32][9];

    int wid  = threadIdx.x >> 5;
    int ps   = wid >> 1;
    int sh   = wid & 1;
    int lane = threadIdx.x & 31;
    int wt   = blockIdx.x * 4 + ps;

    int A = (int)((sqrtf(8.f * (float)wt + 1.f) - 1.f) * 0.5f);
    while ((A + 1) * (A + 2) / 2 <= wt) ++A;
    while (A * (A + 1) / 2 > wt) --A;
    int B = wt - A * (A + 1) / 2;

    const float* px = soa;
    const float* py = soa + NPTS;
    const float* pz = soa + 2 * NPTS;
    const float* nx = soa + 3 * NPTS;
    const float* ny = soa + 4 * NPTS;
    const float* nz = soa + 5 * NPTS;
    const float* ns = soa + 6 * NPTS;

    int ri = B * 32 + lane;
    int rj = A * 32 + lane;
    float pix = __ldg(&px[ri]), piy = __ldg(&py[ri]), piz = __ldg(&pz[ri]);
    float nix = __ldg(&nx[ri]), niy = __ldg(&ny[ri]), niz = __ldg(&nz[ri]);
    float nis = __ldg(&ns[ri]);
    float qjx = __ldg(&px[rj]), qjy = __ldg(&py[rj]), qjz = __ldg(&pz[rj]);
    float mjx = __ldg(&nx[rj]), mjy = __ldg(&ny[rj]), mjz = __ldg(&nz[rj]);
    float mjs = __ldg(&ns[rj]);

    float ai0 = 0.f, ai1 = 0.f, ai2 = 0.f, ai3 = 0.f;
    float aj0 = 0.f, aj1 = 0.f, aj2 = 0.f, aj3 = 0.f;
    int s0i = sh * 16;

    if (A != B) {
        #pragma unroll 4
        for (int s = s0i; s < s0i + 16; ++s) {
            int src = (lane + s) & 31;
            float pjx = __shfl_sync(FULLM, qjx, src);
            float pjy = __shfl_sync(FULLM, qjy, src);
            float pjz = __shfl_sync(FULLM, qjz, src);
            float njx = __shfl_sync(FULLM, mjx, src);
            float njy = __shfl_sync(FULLM, mjy, src);
            float njz = __shfl_sync(FULLM, mjz, src);
            float njs = __shfl_sync(FULLM, mjs, src);

            float dn, a1, a2, a3;
            ppf_pair(pix, piy, piz, nix, niy, niz, nis,
                     pjx, pjy, pjz, njx, njy, njz, njs, dn, a1, a2, a3);

            ai0 += dn; ai1 += a1; ai2 += a2; ai3 += a3;

            float c0 = dn, c1 = PI - a2, c2 = PI - a1, c3 = a3;
            int rsrc = (lane - s) & 31;
            aj0 += __shfl_sync(FULLM, c0, rsrc);
            aj1 += __shfl_sync(FULLM, c1, rsrc);
            aj2 += __shfl_sync(FULLM, c2, rsrc);
            aj3 += __shfl_sync(FULLM, c3, rsrc);
        }
    } else {
        #pragma unroll 4
        for (int s = s0i; s < s0i + 16; ++s) {
            int src = (lane + s) & 31;
            float pjx = __shfl_sync(FULLM, qjx, src);
            float pjy = __shfl_sync(FULLM, qjy, src);
            float pjz = __shfl_sync(FULLM, qjz, src);
            float njx = __shfl_sync(FULLM, mjx, src);
            float njy = __shfl_sync(FULLM, mjy, src);
            float njz = __shfl_sync(FULLM, mjz, src);
            float njs = __shfl_sync(FULLM, mjs, src);

            float dn, a1, a2, a3;
            ppf_pair(pix, piy, piz, nix, niy, niz, nis,
                     pjx, pjy, pjz, njx, njy, njz, njs, dn, a1, a2, a3);

            ai0 += dn; ai1 += a1; ai2 += a2; ai3 += a3;
        }
    }

    if (sh == 1) {
        sbuf[ps][lane][0] = ai0; sbuf[ps][lane][1] = ai1;
        sbuf[ps][lane][2] = ai2; sbuf[ps][lane][3] = ai3;
        sbuf[ps][lane][4] = aj0; sbuf[ps][lane][5] = aj1;
        sbuf[ps][lane][6] = aj2; sbuf[ps][lane][7] = aj3;
    }
    __syncthreads();
    if (sh == 0) {
        ai0 += sbuf[ps][lane][0]; ai1 += sbuf[ps][lane][1];
        ai2 += sbuf[ps][lane][2]; ai3 += sbuf[ps][lane][3];
        aj0 += sbuf[ps][lane][4]; aj1 += sbuf[ps][lane][5];
        aj2 += sbuf[ps][lane][6]; aj3 += sbuf[ps][lane][7];

        part[ri * NTILES + A] = make_float4(ai0, ai1, ai2, ai3);
        if (A != B)
            part[rj * NTILES + B] = make_float4(aj0, aj1, aj2, aj3);
    }
}

// ---------------------------------------------------------------------------
// Kernel C: tree-reduce 64 partials per row + 4->256 linear layer
// ---------------------------------------------------------------------------
__global__ void __launch_bounds__(256)
finalize_kernel(const float4* __restrict__ part,
                const float* __restrict__ W, const float* __restrict__ b,
                float* __restrict__ out) {
    __shared__ float4 wsum[2];
    __shared__ float feat[4];
    int i = blockIdx.x, t = threadIdx.x;

    if (t < 64) {
        float4 v = part[i * NTILES + t];
        #pragma unroll
        for (int off = 16; off > 0; off >>= 1) {
            v.x += __shfl_down_sync(FULLM, v.x, off);
            v.y += __shfl_down_sync(FULLM, v.y, off);
            v.z += __shfl_down_sync(FULLM, v.z, off);
            v.w += __shfl_down_sync(FULLM, v.w, off);
        }
        if ((t & 31) == 0) wsum[t >> 5] = v;
    }
    __syncthreads();
    if (t == 0) {
        float4 a = wsum[0], c = wsum[1];
        feat[0] = (a.x + c.x) / 2048.f;
        feat[1] = (a.y + c.y) / 2048.f;
        feat[2] = (a.z + c.z) / 2048.f;
        feat[3] = (a.w + c.w) / 2048.f;
    }
    __syncthreads();
    float f0 = feat[0], f1 = feat[1], f2 = feat[2], f3 = feat[3];
    float acc = f0 * W[t * 4 + 0];
    acc = acc + f1 * W[t * 4 + 1];
    acc = acc + f2 * W[t * 4 + 2];
    acc = acc + f3 * W[t * 4 + 3];
    acc = acc + b[t];
    out[i * OUTF + t] = acc;
}

extern "C" void kernel_launch(void* const* d_in, const int* in_sizes, int n_in,
                              void* d_out, int out_size) {
    const float* points = (const float*)d_in[0];   // (1, 2048, 3)
    const float* W      = (const float*)d_in[1];   // (256, 4)
    const float* b      = (const float*)d_in[2];   // (256,)
    float* out          = (float*)d_out;           // (1, 2048, 256)
    (void)in_sizes; (void)n_in; (void)out_size;

    float* soa; float4* part;
    cudaGetSymbolAddress((void**)&soa, g_soa);
    cudaGetSymbolAddress((void**)&part, g_part);

    knn_normals_kernel<<<NPTS / 4, 256>>>(points, soa);
    sym_ppf_kernel<<<NTPAIRS / 4, 256>>>(soa, part);
    finalize_kernel<<<NPTS, 256>>>(part, W, b, out);
}